// round 1
// baseline (speedup 1.0000x reference)
#include <cuda_runtime.h>

static constexpr int Bn = 8, Tn = 1024, Cn = 768, Hn = 12, Dn = 64;
static constexpr int Mn = Bn * Tn; // 8192 rows

// Scratch (device globals — no runtime allocation allowed)
__device__ float g_q[Mn * Cn];
__device__ float g_k[Mn * Cn];
__device__ float g_v[Mn * Cn];
__device__ float g_y[Mn * Cn];

// ---------------------------------------------------------------------------
// 128x128x16 fp32 GEMM tile: Out[M,N] = A[M,K] @ W[K,N] + bias
// 256 threads, each computes an 8x8 microtile.
// ---------------------------------------------------------------------------
__device__ __forceinline__ void gemm_tile(const float* __restrict__ A,
                                          const float* __restrict__ W,
                                          const float* __restrict__ bias,
                                          float* __restrict__ Out)
{
    constexpr int K = Cn, N = Cn;
    __shared__ float As[16][128];
    __shared__ float Bs[16][128];

    const int tid = threadIdx.x;
    const int ty  = tid >> 4;
    const int tx  = tid & 15;
    const int bm  = blockIdx.y * 128;
    const int bn  = blockIdx.x * 128;

    float acc[8][8];
#pragma unroll
    for (int i = 0; i < 8; i++)
#pragma unroll
        for (int j = 0; j < 8; j++) acc[i][j] = 0.f;

    const int ar  = tid >> 2;          // A row (0..63), +64 for second half
    const int ak  = (tid & 3) << 2;    // k offset within 16-wide tile
    const int bkr = tid >> 5;          // B k-row (0..7), +8 for second half
    const int bnc = (tid & 31) << 2;   // B col offset

    for (int k0 = 0; k0 < K; k0 += 16) {
#pragma unroll
        for (int i = 0; i < 2; i++) {
            int row = ar + i * 64;
            float4 a4 = *(const float4*)(A + (bm + row) * K + k0 + ak);
            As[ak + 0][row] = a4.x;
            As[ak + 1][row] = a4.y;
            As[ak + 2][row] = a4.z;
            As[ak + 3][row] = a4.w;
        }
#pragma unroll
        for (int i = 0; i < 2; i++) {
            int kr = bkr + i * 8;
            *(float4*)(&Bs[kr][bnc]) = *(const float4*)(W + (k0 + kr) * N + bn + bnc);
        }
        __syncthreads();
#pragma unroll
        for (int kk = 0; kk < 16; kk++) {
            float a[8], b[8];
            *(float4*)&a[0] = *(const float4*)&As[kk][ty * 8];
            *(float4*)&a[4] = *(const float4*)&As[kk][ty * 8 + 4];
            *(float4*)&b[0] = *(const float4*)&Bs[kk][tx * 8];
            *(float4*)&b[4] = *(const float4*)&Bs[kk][tx * 8 + 4];
#pragma unroll
            for (int i = 0; i < 8; i++)
#pragma unroll
                for (int j = 0; j < 8; j++) acc[i][j] += a[i] * b[j];
        }
        __syncthreads();
    }

#pragma unroll
    for (int i = 0; i < 8; i++) {
        int row = bm + ty * 8 + i;
#pragma unroll
        for (int j4 = 0; j4 < 8; j4 += 4) {
            int col = bn + tx * 8 + j4;
            float4 r;
            r.x = acc[i][j4 + 0] + bias[col + 0];
            r.y = acc[i][j4 + 1] + bias[col + 1];
            r.z = acc[i][j4 + 2] + bias[col + 2];
            r.w = acc[i][j4 + 3] + bias[col + 3];
            *(float4*)(Out + row * N + col) = r;
        }
    }
}

__global__ __launch_bounds__(256, 2)
void qkv_kernel(const float* __restrict__ x,
                const float* __restrict__ Wq, const float* __restrict__ bq,
                const float* __restrict__ Wk, const float* __restrict__ bk,
                const float* __restrict__ Wv, const float* __restrict__ bv)
{
    const float* W; const float* bb; float* Out;
    if (blockIdx.z == 0)      { W = Wq; bb = bq; Out = g_q; }
    else if (blockIdx.z == 1) { W = Wk; bb = bk; Out = g_k; }
    else                      { W = Wv; bb = bv; Out = g_v; }
    gemm_tile(x, W, bb, Out);
}

__global__ __launch_bounds__(256, 2)
void proj_kernel(const float* __restrict__ Wp, const float* __restrict__ bp,
                 float* __restrict__ out)
{
    gemm_tile(g_y, Wp, bp, out);
}

// ---------------------------------------------------------------------------
// Flash attention: one block per (q-tile=64, head, batch).
// 256 threads; thread (ty,tx) owns rows ty*4..+3. S cols = {tx, 16+tx, 32+tx, 48+tx}.
// O dims = tx*4..+3. K stored with float4-unit XOR swizzle (conflict-free reads,
// no padding -> sQ+sK+sV = exactly 48KB static smem; P reuses the K buffer).
// ---------------------------------------------------------------------------
__global__ __launch_bounds__(256)
void attn_kernel()
{
    __shared__ float sQ[64 * 64];
    __shared__ float sK[64 * 64];  // swizzled K; reused as P after barrier
    __shared__ float sV[64 * 64];

    const int tid = threadIdx.x;
    const int ty  = tid >> 4;
    const int tx  = tid & 15;
    const int qt  = blockIdx.x;
    const int h   = blockIdx.y;
    const int b   = blockIdx.z;
    const int qbase = qt * 64;
    const int r0    = ty * 4;

    const float* Qg = g_q + (b * Tn) * Cn + h * Dn;
    const float* Kg = g_k + (b * Tn) * Cn + h * Dn;
    const float* Vg = g_v + (b * Tn) * Cn + h * Dn;

    // Load Q tile [64 x 64] (plain layout)
    for (int i = tid; i < 64 * 16; i += 256) {
        int r  = i >> 4;
        int c4 = (i & 15) << 2;
        *(float4*)&sQ[r * 64 + c4] = *(const float4*)(Qg + (qbase + r) * Cn + c4);
    }

    float m[4], l[4], o[4][4];
#pragma unroll
    for (int i = 0; i < 4; i++) {
        m[i] = -1e30f; l[i] = 0.f;
#pragma unroll
        for (int j = 0; j < 4; j++) o[i][j] = 0.f;
    }

    for (int kb = 0; kb <= qbase; kb += 64) {
        __syncthreads();  // prev-iter P/V readers done before overwrite
        // Load K (XOR-swizzled float4 units) and V (plain)
        for (int i = tid; i < 64 * 16; i += 256) {
            int r  = i >> 4;
            int u  = i & 15;
            float4 kv = *(const float4*)(Kg + (kb + r) * Cn + (u << 2));
            *(float4*)&sK[r * 64 + ((u ^ (r & 15)) << 2)] = kv;
            *(float4*)&sV[r * 64 + (u << 2)] =
                *(const float4*)(Vg + (kb + r) * Cn + (u << 2));
        }
        __syncthreads();

        // S = Q @ K^T (per-thread 4x4)
        float s[4][4];
#pragma unroll
        for (int i = 0; i < 4; i++)
#pragma unroll
            for (int j = 0; j < 4; j++) s[i][j] = 0.f;

#pragma unroll
        for (int d0 = 0; d0 < 64; d0 += 4) {
            float q[4][4];
#pragma unroll
            for (int i = 0; i < 4; i++)
                *(float4*)q[i] = *(const float4*)&sQ[(r0 + i) * 64 + d0];
            const int uoff = (((d0 >> 2) ^ tx) << 2);  // swizzle: (col & 15) == tx
#pragma unroll
            for (int j = 0; j < 4; j++) {
                const float* kp = &sK[(j * 16 + tx) * 64 + uoff];
#pragma unroll
                for (int e = 0; e < 4; e++) {
                    float kv = kp[e];
#pragma unroll
                    for (int i = 0; i < 4; i++) s[i][j] += q[i][e] * kv;
                }
            }
        }

        // Scale + causal mask (only the diagonal tile needs masking)
        const bool diag = (kb == qbase);
#pragma unroll
        for (int i = 0; i < 4; i++)
#pragma unroll
            for (int j = 0; j < 4; j++) {
                float sv = s[i][j] * 0.125f;  // 1/sqrt(64)
                if (diag && (j * 16 + tx > r0 + i)) sv = -1e30f;
                s[i][j] = sv;
            }

        // Online softmax (row reductions over 16 lanes)
#pragma unroll
        for (int i = 0; i < 4; i++) {
            float tm = fmaxf(fmaxf(s[i][0], s[i][1]), fmaxf(s[i][2], s[i][3]));
#pragma unroll
            for (int off = 8; off > 0; off >>= 1)
                tm = fmaxf(tm, __shfl_xor_sync(0xffffffffu, tm, off));
            float mn  = fmaxf(m[i], tm);
            float fac = __expf(m[i] - mn);
            m[i] = mn;
            float rs = 0.f;
#pragma unroll
            for (int j = 0; j < 4; j++) {
                float p = __expf(s[i][j] - mn);
                s[i][j] = p;
                rs += p;
            }
#pragma unroll
            for (int off = 8; off > 0; off >>= 1)
                rs += __shfl_xor_sync(0xffffffffu, rs, off);
            l[i] = l[i] * fac + rs;
#pragma unroll
            for (int j = 0; j < 4; j++) o[i][j] *= fac;
        }

        __syncthreads();  // all S reads of sK done — safe to overwrite with P
#pragma unroll
        for (int i = 0; i < 4; i++)
#pragma unroll
            for (int j = 0; j < 4; j++)
                sK[(r0 + i) * 64 + j * 16 + tx] = s[i][j];
        __syncthreads();

        // O += P @ V
#pragma unroll
        for (int c0 = 0; c0 < 64; c0 += 4) {
            float p[4][4], v[4][4];
#pragma unroll
            for (int i = 0; i < 4; i++)
                *(float4*)p[i] = *(const float4*)&sK[(r0 + i) * 64 + c0];
#pragma unroll
            for (int e = 0; e < 4; e++)
                *(float4*)v[e] = *(const float4*)&sV[(c0 + e) * 64 + tx * 4];
#pragma unroll
            for (int e = 0; e < 4; e++)
#pragma unroll
                for (int i = 0; i < 4; i++)
#pragma unroll
                    for (int j = 0; j < 4; j++)
                        o[i][j] += p[i][e] * v[e][j];
        }
    }

    // Normalize + write y (head-merged layout [B*T, C])
#pragma unroll
    for (int i = 0; i < 4; i++) {
        float inv = 1.f / l[i];
        float4 r;
        r.x = o[i][0] * inv; r.y = o[i][1] * inv;
        r.z = o[i][2] * inv; r.w = o[i][3] * inv;
        *(float4*)(g_y + ((b * Tn) + qbase + r0 + i) * Cn + h * Dn + tx * 4) = r;
    }
}

// ---------------------------------------------------------------------------
extern "C" void kernel_launch(void* const* d_in, const int* in_sizes, int n_in,
                              void* d_out, int out_size)
{
    const float* x  = (const float*)d_in[0];
    const float* Wq = (const float*)d_in[1];
    const float* bq = (const float*)d_in[2];
    const float* Wk = (const float*)d_in[3];
    const float* bk = (const float*)d_in[4];
    const float* Wv = (const float*)d_in[5];
    const float* bv = (const float*)d_in[6];
    const float* Wp = (const float*)d_in[7];
    const float* bp = (const float*)d_in[8];
    float* out = (float*)d_out;

    qkv_kernel<<<dim3(Cn / 128, Mn / 128, 3), 256>>>(x, Wq, bq, Wk, bk, Wv, bv);
    attn_kernel<<<dim3(Tn / 64, Hn, Bn), 256>>>();
    proj_kernel<<<dim3(Cn / 128, Mn / 128), 256>>>(Wp, bp, out);
}

// round 3
// speedup vs baseline: 1.6673x; 1.6673x over previous
#include <cuda_runtime.h>
#include <cuda_bf16.h>
#include <cstdint>

static constexpr int Bn = 8, Tn = 1024, Cn = 768, Hn = 12, Dn = 64;
static constexpr int Mn = Bn * Tn;      // 8192
static constexpr int KT = Cn / 16;      // 48 k16 chunks
static constexpr int MT = Mn / 16;      // 512 m16 tiles
static constexpr int NTW = Cn / 8;      // 96 n8 tiles per weight matrix

// ---------------------------------------------------------------------------
// Scratch device globals (no runtime allocation allowed)
// ---------------------------------------------------------------------------
__device__ float g_q[Mn * Cn];
__device__ float g_k[Mn * Cn];
__device__ float g_v[Mn * Cn];
__device__ float g_y[Mn * Cn];

// Fragment-major pre-split activations: [m16tile][k16chunk][lane] -> uint4
// uint4 = {a0,a1,a2,a3} bf16x2 regs of the m16n8k16 A fragment.
__device__ uint4 g_xfh[MT * KT * 32];
__device__ uint4 g_xfl[MT * KT * 32];
__device__ uint4 g_yfh[MT * KT * 32];
__device__ uint4 g_yfl[MT * KT * 32];
// Weights: [mat][n8tile][k16chunk][lane] -> uint4 {bh0,bh1,bl0,bl1}
__device__ uint4 g_wf[4 * NTW * KT * 32];

// ---------------------------------------------------------------------------
// Helpers
// ---------------------------------------------------------------------------
__device__ __forceinline__ uint32_t smem_u32(const void* p) {
    uint32_t a;
    asm("{ .reg .u64 t; cvta.to.shared.u64 t, %1; cvt.u32.u64 %0, t; }"
        : "=r"(a) : "l"(p));
    return a;
}

__device__ __forceinline__ void cp16(uint32_t dst, const void* src) {
    asm volatile("cp.async.ca.shared.global [%0], [%1], 16;\n"
                 :: "r"(dst), "l"(src));
}
#define CP_COMMIT() asm volatile("cp.async.commit_group;\n" ::: "memory")
#define CP_WAIT2()  asm volatile("cp.async.wait_group 2;\n" ::: "memory")

__device__ __forceinline__ void mma16816(float* d, const uint32_t* a,
                                         uint32_t b0, uint32_t b1) {
    asm volatile(
        "mma.sync.aligned.m16n8k16.row.col.f32.bf16.bf16.f32 "
        "{%0,%1,%2,%3}, {%4,%5,%6,%7}, {%8,%9}, {%0,%1,%2,%3};\n"
        : "+f"(d[0]), "+f"(d[1]), "+f"(d[2]), "+f"(d[3])
        : "r"(a[0]), "r"(a[1]), "r"(a[2]), "r"(a[3]), "r"(b0), "r"(b1));
}

// Split two floats into packed bf16x2 hi and lo (lo = residual)
__device__ __forceinline__ void split2(float x, float y, uint32_t& h, uint32_t& l) {
    __nv_bfloat16 hx = __float2bfloat16_rn(x);
    __nv_bfloat16 hy = __float2bfloat16_rn(y);
    float lx = x - __bfloat162float(hx);
    float ly = y - __bfloat162float(hy);
    __nv_bfloat16 lxh = __float2bfloat16_rn(lx);
    __nv_bfloat16 lyh = __float2bfloat16_rn(ly);
    h = (uint32_t)__bfloat16_as_ushort(hx) | ((uint32_t)__bfloat16_as_ushort(hy) << 16);
    l = (uint32_t)__bfloat16_as_ushort(lxh) | ((uint32_t)__bfloat16_as_ushort(lyh) << 16);
}

// ---------------------------------------------------------------------------
// Activation split: fp32 [Mn][Cn] -> fragment-major bf16 hi/lo
// One warp per (m16tile, k16chunk).
// ---------------------------------------------------------------------------
__global__ __launch_bounds__(256)
void split_act_kernel(const float* __restrict__ X, uint4* __restrict__ dh,
                      uint4* __restrict__ dl)
{
    int w = (blockIdx.x * 256 + threadIdx.x) >> 5;
    int lane = threadIdx.x & 31;
    if (w >= MT * KT) return;
    int tm = w / KT, tk = w % KT;
    int row = tm * 16 + (lane >> 2);
    int kc  = tk * 16 + ((lane & 3) << 1);

    float2 v00 = *(const float2*)(X + (size_t)row * Cn + kc);
    float2 v10 = *(const float2*)(X + (size_t)(row + 8) * Cn + kc);
    float2 v01 = *(const float2*)(X + (size_t)row * Cn + kc + 8);
    float2 v11 = *(const float2*)(X + (size_t)(row + 8) * Cn + kc + 8);

    uint4 h, l;
    split2(v00.x, v00.y, h.x, l.x);
    split2(v10.x, v10.y, h.y, l.y);
    split2(v01.x, v01.y, h.z, l.z);
    split2(v11.x, v11.y, h.w, l.w);
    size_t o = (size_t)w * 32 + lane;
    dh[o] = h;
    dl[o] = l;
}

// ---------------------------------------------------------------------------
// Weight split: W[k][n] fp32 -> B fragment-major {bh0,bh1,bl0,bl1}
// One warp per (mat, n8tile, k16chunk).
// ---------------------------------------------------------------------------
__global__ __launch_bounds__(256)
void split_w_kernel(const float* __restrict__ Wq, const float* __restrict__ Wk,
                    const float* __restrict__ Wv, const float* __restrict__ Wp)
{
    int w = (blockIdx.x * 256 + threadIdx.x) >> 5;
    int lane = threadIdx.x & 31;
    if (w >= 4 * NTW * KT) return;
    int mat = w / (NTW * KT);
    int rem = w % (NTW * KT);
    int tn = rem / KT, tk = rem % KT;

    const float* W;
    switch (mat) {
        case 0: W = Wq; break;
        case 1: W = Wk; break;
        case 2: W = Wv; break;
        default: W = Wp; break;
    }
    int n  = tn * 8 + (lane >> 2);
    int k0 = tk * 16 + ((lane & 3) << 1);

    float b00 = W[(size_t)k0 * Cn + n];
    float b01 = W[(size_t)(k0 + 1) * Cn + n];
    float b10 = W[(size_t)(k0 + 8) * Cn + n];
    float b11 = W[(size_t)(k0 + 9) * Cn + n];

    uint4 o;
    split2(b00, b01, o.x, o.z);
    split2(b10, b11, o.y, o.w);
    g_wf[(size_t)w * 32 + lane] = o;
}

// ---------------------------------------------------------------------------
// bf16x3 tensor-core GEMM: Out[128,128]tile = A[128,768] @ W[768,128] + bias
// 256 threads (8 warps: 4m x 2n, warp tile 32x64). 4-stage cp.async pipeline.
// Dynamic smem: 4 stages x (A 8KB + B 8KB) = 64KB.
// Stage layout: [0,4K)=A_hi [4K,8K)=A_lo (mt*512+lane*16), [8K,16K)=B (nt*512+lane*16)
// ---------------------------------------------------------------------------
static constexpr int STG_BYTES = 16384;
static constexpr int GEMM_SMEM = 4 * STG_BYTES;

__device__ __forceinline__ void gemm_mma_body(const uint4* __restrict__ Ah,
                                              const uint4* __restrict__ Al,
                                              const uint4* __restrict__ Wf,
                                              const float* __restrict__ bias,
                                              float* __restrict__ Out)
{
    extern __shared__ __align__(16) char smem[];
    const uint32_t sbase = smem_u32(smem);
    const int tid  = threadIdx.x;
    const int lane = tid & 31;
    const int wid  = tid >> 5;
    const int wm   = wid >> 1;   // 0..3
    const int wn   = wid & 1;    // 0..1

    const int mtBase = blockIdx.y * 8;    // m16 tiles
    const int ntBase = blockIdx.x * 16;   // n8 tiles

    // per-thread copy roles
    const int cp_mt   = tid >> 5;         // 0..7
    const int cp_lane = lane;

    // gmem source bases for this thread's copy slots
    const uint4* srcAh = Ah + ((size_t)(mtBase + cp_mt) * KT) * 32 + cp_lane;
    const uint4* srcAl = Al + ((size_t)(mtBase + cp_mt) * KT) * 32 + cp_lane;
    const uint4* srcB0 = Wf + ((size_t)(ntBase + cp_mt) * KT) * 32 + cp_lane;
    const uint4* srcB1 = Wf + ((size_t)(ntBase + cp_mt + 8) * KT) * 32 + cp_lane;

    const uint32_t dA0 = sbase + cp_mt * 512 + cp_lane * 16;
    const uint32_t dA1 = dA0 + 4096;
    const uint32_t dB0 = sbase + 8192 + cp_mt * 512 + cp_lane * 16;
    const uint32_t dB1 = dB0 + 8 * 512;

    float d[2][8][4];
#pragma unroll
    for (int i = 0; i < 2; i++)
#pragma unroll
        for (int j = 0; j < 8; j++)
#pragma unroll
            for (int e = 0; e < 4; e++) d[i][j][e] = 0.f;

    auto issue = [&](int slot, int tk) {
        uint32_t so = (uint32_t)slot * STG_BYTES;
        cp16(dA0 + so, srcAh + (size_t)tk * 32);
        cp16(dA1 + so, srcAl + (size_t)tk * 32);
        cp16(dB0 + so, srcB0 + (size_t)tk * 32);
        cp16(dB1 + so, srcB1 + (size_t)tk * 32);
    };

    issue(0, 0); CP_COMMIT();
    issue(1, 1); CP_COMMIT();
    issue(2, 2); CP_COMMIT();

    const char* sA = smem;                 // A region base
    for (int k = 0; k < KT; k++) {
        CP_WAIT2();
        __syncthreads();
        if (k + 3 < KT) issue((k + 3) & 3, k + 3);
        CP_COMMIT();

        const char* stg = sA + (size_t)(k & 3) * STG_BYTES;
        // A fragments (2 m-tiles, hi+lo)
        uint4 ah0 = *(const uint4*)(stg + (wm * 2 + 0) * 512 + lane * 16);
        uint4 ah1 = *(const uint4*)(stg + (wm * 2 + 1) * 512 + lane * 16);
        uint4 al0 = *(const uint4*)(stg + 4096 + (wm * 2 + 0) * 512 + lane * 16);
        uint4 al1 = *(const uint4*)(stg + 4096 + (wm * 2 + 1) * 512 + lane * 16);
#pragma unroll
        for (int nt = 0; nt < 8; nt++) {
            uint4 b = *(const uint4*)(stg + 8192 + (wn * 8 + nt) * 512 + lane * 16);
            mma16816(d[0][nt], (const uint32_t*)&ah0, b.x, b.y);  // ah*bh
            mma16816(d[0][nt], (const uint32_t*)&ah0, b.z, b.w);  // ah*bl
            mma16816(d[0][nt], (const uint32_t*)&al0, b.x, b.y);  // al*bh
            mma16816(d[1][nt], (const uint32_t*)&ah1, b.x, b.y);
            mma16816(d[1][nt], (const uint32_t*)&ah1, b.z, b.w);
            mma16816(d[1][nt], (const uint32_t*)&al1, b.x, b.y);
        }
    }

    // Epilogue
    const int rbase = blockIdx.y * 128 + wm * 32 + (lane >> 2);
    const int cb    = blockIdx.x * 128 + wn * 64 + ((lane & 3) << 1);
#pragma unroll
    for (int mt = 0; mt < 2; mt++) {
#pragma unroll
        for (int nt = 0; nt < 8; nt++) {
            int col = cb + nt * 8;
            float bx = bias[col], by = bias[col + 1];
            int r0 = rbase + mt * 16;
            float2 v0 = make_float2(d[mt][nt][0] + bx, d[mt][nt][1] + by);
            float2 v1 = make_float2(d[mt][nt][2] + bx, d[mt][nt][3] + by);
            *(float2*)(Out + (size_t)r0 * Cn + col) = v0;
            *(float2*)(Out + (size_t)(r0 + 8) * Cn + col) = v1;
        }
    }
}

__global__ __launch_bounds__(256, 1)
void qkv_mma(const float* __restrict__ bq, const float* __restrict__ bk,
             const float* __restrict__ bv)
{
    const uint4* Wf = g_wf + (size_t)blockIdx.z * NTW * KT * 32;
    const float* bb;
    float* Out;
    if (blockIdx.z == 0)      { bb = bq; Out = g_q; }
    else if (blockIdx.z == 1) { bb = bk; Out = g_k; }
    else                      { bb = bv; Out = g_v; }
    gemm_mma_body(g_xfh, g_xfl, Wf, bb, Out);
}

__global__ __launch_bounds__(256, 1)
void proj_mma(const float* __restrict__ bp, float* __restrict__ out)
{
    gemm_mma_body(g_yfh, g_yfl, g_wf + (size_t)3 * NTW * KT * 32, bp, out);
}

// ---------------------------------------------------------------------------
// Flash attention (unchanged, passing at ~525us): block per (qtile64, head, b)
// ---------------------------------------------------------------------------
__global__ __launch_bounds__(256)
void attn_kernel()
{
    __shared__ float sQ[64 * 64];
    __shared__ float sK[64 * 64];
    __shared__ float sV[64 * 64];

    const int tid = threadIdx.x;
    const int ty  = tid >> 4;
    const int tx  = tid & 15;
    const int qbase = blockIdx.x * 64;
    const int h   = blockIdx.y;
    const int b   = blockIdx.z;
    const int r0  = ty * 4;

    const float* Qg = g_q + (b * Tn) * Cn + h * Dn;
    const float* Kg = g_k + (b * Tn) * Cn + h * Dn;
    const float* Vg = g_v + (b * Tn) * Cn + h * Dn;

    for (int i = tid; i < 64 * 16; i += 256) {
        int r  = i >> 4;
        int c4 = (i & 15) << 2;
        *(float4*)&sQ[r * 64 + c4] = *(const float4*)(Qg + (qbase + r) * Cn + c4);
    }

    float m[4], l[4], o[4][4];
#pragma unroll
    for (int i = 0; i < 4; i++) {
        m[i] = -1e30f; l[i] = 0.f;
#pragma unroll
        for (int j = 0; j < 4; j++) o[i][j] = 0.f;
    }

    for (int kb = 0; kb <= qbase; kb += 64) {
        __syncthreads();
        for (int i = tid; i < 64 * 16; i += 256) {
            int r = i >> 4;
            int u = i & 15;
            float4 kv = *(const float4*)(Kg + (kb + r) * Cn + (u << 2));
            *(float4*)&sK[r * 64 + ((u ^ (r & 15)) << 2)] = kv;
            *(float4*)&sV[r * 64 + (u << 2)] =
                *(const float4*)(Vg + (kb + r) * Cn + (u << 2));
        }
        __syncthreads();

        float s[4][4];
#pragma unroll
        for (int i = 0; i < 4; i++)
#pragma unroll
            for (int j = 0; j < 4; j++) s[i][j] = 0.f;

#pragma unroll
        for (int d0 = 0; d0 < 64; d0 += 4) {
            float q[4][4];
#pragma unroll
            for (int i = 0; i < 4; i++)
                *(float4*)q[i] = *(const float4*)&sQ[(r0 + i) * 64 + d0];
            const int uoff = (((d0 >> 2) ^ tx) << 2);
#pragma unroll
            for (int j = 0; j < 4; j++) {
                const float* kp = &sK[(j * 16 + tx) * 64 + uoff];
#pragma unroll
                for (int e = 0; e < 4; e++) {
                    float kv = kp[e];
#pragma unroll
                    for (int i = 0; i < 4; i++) s[i][j] += q[i][e] * kv;
                }
            }
        }

        const bool diag = (kb == qbase);
#pragma unroll
        for (int i = 0; i < 4; i++)
#pragma unroll
            for (int j = 0; j < 4; j++) {
                float sv = s[i][j] * 0.125f;
                if (diag && (j * 16 + tx > r0 + i)) sv = -1e30f;
                s[i][j] = sv;
            }

#pragma unroll
        for (int i = 0; i < 4; i++) {
            float tm = fmaxf(fmaxf(s[i][0], s[i][1]), fmaxf(s[i][2], s[i][3]));
#pragma unroll
            for (int off = 8; off > 0; off >>= 1)
                tm = fmaxf(tm, __shfl_xor_sync(0xffffffffu, tm, off));
            float mn  = fmaxf(m[i], tm);
            float fac = __expf(m[i] - mn);
            m[i] = mn;
            float rs = 0.f;
#pragma unroll
            for (int j = 0; j < 4; j++) {
                float p = __expf(s[i][j] - mn);
                s[i][j] = p;
                rs += p;
            }
#pragma unroll
            for (int off = 8; off > 0; off >>= 1)
                rs += __shfl_xor_sync(0xffffffffu, rs, off);
            l[i] = l[i] * fac + rs;
#pragma unroll
            for (int j = 0; j < 4; j++) o[i][j] *= fac;
        }

        __syncthreads();
#pragma unroll
        for (int i = 0; i < 4; i++)
#pragma unroll
            for (int j = 0; j < 4; j++)
                sK[(r0 + i) * 64 + j * 16 + tx] = s[i][j];
        __syncthreads();

#pragma unroll
        for (int c0 = 0; c0 < 64; c0 += 4) {
            float p[4][4], v[4][4];
#pragma unroll
            for (int i = 0; i < 4; i++)
                *(float4*)p[i] = *(const float4*)&sK[(r0 + i) * 64 + c0];
#pragma unroll
            for (int e = 0; e < 4; e++)
                *(float4*)v[e] = *(const float4*)&sV[(c0 + e) * 64 + tx * 4];
#pragma unroll
            for (int e = 0; e < 4; e++)
#pragma unroll
                for (int i = 0; i < 4; i++)
#pragma unroll
                    for (int j = 0; j < 4; j++)
                        o[i][j] += p[i][e] * v[e][j];
        }
    }

#pragma unroll
    for (int i = 0; i < 4; i++) {
        float inv = 1.f / l[i];
        float4 r;
        r.x = o[i][0] * inv; r.y = o[i][1] * inv;
        r.z = o[i][2] * inv; r.w = o[i][3] * inv;
        *(float4*)(g_y + ((b * Tn) + qbase + r0 + i) * Cn + h * Dn + tx * 4) = r;
    }
}

// ---------------------------------------------------------------------------
extern "C" void kernel_launch(void* const* d_in, const int* in_sizes, int n_in,
                              void* d_out, int out_size)
{
    const float* x  = (const float*)d_in[0];
    const float* Wq = (const float*)d_in[1];
    const float* bq = (const float*)d_in[2];
    const float* Wk = (const float*)d_in[3];
    const float* bk = (const float*)d_in[4];
    const float* Wv = (const float*)d_in[5];
    const float* bv = (const float*)d_in[6];
    const float* Wp = (const float*)d_in[7];
    const float* bp = (const float*)d_in[8];
    float* out = (float*)d_out;

    cudaFuncSetAttribute(qkv_mma, cudaFuncAttributeMaxDynamicSharedMemorySize, GEMM_SMEM);
    cudaFuncSetAttribute(proj_mma, cudaFuncAttributeMaxDynamicSharedMemorySize, GEMM_SMEM);

    uint4 *xfh, *xfl, *yfh, *yfl;
    cudaGetSymbolAddress((void**)&xfh, g_xfh);
    cudaGetSymbolAddress((void**)&xfl, g_xfl);
    cudaGetSymbolAddress((void**)&yfh, g_yfh);
    cudaGetSymbolAddress((void**)&yfl, g_yfl);
    float* yp;
    cudaGetSymbolAddress((void**)&yp, g_y);

    split_act_kernel<<<(MT * KT) / 8, 256>>>(x, xfh, xfl);
    split_w_kernel<<<(4 * NTW * KT) / 8, 256>>>(Wq, Wk, Wv, Wp);
    qkv_mma<<<dim3(Cn / 128, Mn / 128, 3), 256, GEMM_SMEM>>>(bq, bk, bv);
    attn_kernel<<<dim3(Tn / 64, Hn, Bn), 256>>>();
    split_act_kernel<<<(MT * KT) / 8, 256>>>(yp, yfh, yfl);
    proj_mma<<<dim3(Cn / 128, Mn / 128, 1), 256, GEMM_SMEM>>>(bp, out);
}

// round 4
// speedup vs baseline: 2.4014x; 1.4403x over previous
#include <cuda_runtime.h>
#include <cuda_bf16.h>
#include <cstdint>

static constexpr int Bn = 8, Tn = 1024, Cn = 768, Hn = 12, Dn = 64;
static constexpr int Mn = Bn * Tn;      // 8192
static constexpr int KT = Cn / 16;      // 48 k16 chunks
static constexpr int MT = Mn / 16;      // 512 m16 tiles
static constexpr int NTW = Cn / 8;      // 96 n8 tiles per weight matrix
static constexpr int BH = Bn * Hn;      // 96

// ---------------------------------------------------------------------------
// Scratch device globals (no runtime allocation allowed)
// ---------------------------------------------------------------------------
__device__ float g_q[Mn * Cn];
__device__ float g_k[Mn * Cn];
__device__ float g_v[Mn * Cn];
__device__ float g_y[Mn * Cn];

// GEMM fragment buffers (input x, attention output y, weights)
__device__ uint4 g_xfh[MT * KT * 32];
__device__ uint4 g_xfl[MT * KT * 32];
__device__ uint4 g_yfh[MT * KT * 32];
__device__ uint4 g_yfl[MT * KT * 32];
__device__ uint4 g_wf[4 * NTW * KT * 32];

// Attention fragment buffers
// Qf: [bh][mt(64)][dc(4)][lane]  A-frag (hi / lo), pre-scaled by 1/8
__device__ uint4 g_qfh[BH * 64 * 4 * 32];
__device__ uint4 g_qfl[BH * 64 * 4 * 32];
// Kf: [bh][nt(128)][dc(4)][lane] B-frag {bh0,bh1,bl0,bl1}, n=key, k=d
__device__ uint4 g_kf[BH * 128 * 4 * 32];
// Vtf: [bh][dt(8)][kc(64)][lane] B-frag {bh0,bh1,bl0,bl1}, n=d, k=key
__device__ uint4 g_vtf[BH * 8 * 64 * 32];

// ---------------------------------------------------------------------------
// Helpers
// ---------------------------------------------------------------------------
__device__ __forceinline__ uint32_t smem_u32(const void* p) {
    uint32_t a;
    asm("{ .reg .u64 t; cvta.to.shared.u64 t, %1; cvt.u32.u64 %0, t; }"
        : "=r"(a) : "l"(p));
    return a;
}

__device__ __forceinline__ void cp16(uint32_t dst, const void* src) {
    asm volatile("cp.async.ca.shared.global [%0], [%1], 16;\n"
                 :: "r"(dst), "l"(src));
}
#define CP_COMMIT() asm volatile("cp.async.commit_group;\n" ::: "memory")
#define CP_WAIT2()  asm volatile("cp.async.wait_group 2;\n" ::: "memory")
#define CP_WAIT1()  asm volatile("cp.async.wait_group 1;\n" ::: "memory")

__device__ __forceinline__ void mma16816(float* d, const uint32_t* a,
                                         uint32_t b0, uint32_t b1) {
    asm volatile(
        "mma.sync.aligned.m16n8k16.row.col.f32.bf16.bf16.f32 "
        "{%0,%1,%2,%3}, {%4,%5,%6,%7}, {%8,%9}, {%0,%1,%2,%3};\n"
        : "+f"(d[0]), "+f"(d[1]), "+f"(d[2]), "+f"(d[3])
        : "r"(a[0]), "r"(a[1]), "r"(a[2]), "r"(a[3]), "r"(b0), "r"(b1));
}

// Split two floats into packed bf16x2 hi (x in low half) and lo residual.
__device__ __forceinline__ void split2(float x, float y, uint32_t& h, uint32_t& l) {
    __nv_bfloat16 hx = __float2bfloat16_rn(x);
    __nv_bfloat16 hy = __float2bfloat16_rn(y);
    float lx = x - __bfloat162float(hx);
    float ly = y - __bfloat162float(hy);
    __nv_bfloat16 lxh = __float2bfloat16_rn(lx);
    __nv_bfloat16 lyh = __float2bfloat16_rn(ly);
    h = (uint32_t)__bfloat16_as_ushort(hx) | ((uint32_t)__bfloat16_as_ushort(hy) << 16);
    l = (uint32_t)__bfloat16_as_ushort(lxh) | ((uint32_t)__bfloat16_as_ushort(lyh) << 16);
}

// ---------------------------------------------------------------------------
// GEMM-side split kernels (unchanged from R3)
// ---------------------------------------------------------------------------
__global__ __launch_bounds__(256)
void split_act_kernel(const float* __restrict__ X, uint4* __restrict__ dh,
                      uint4* __restrict__ dl)
{
    int w = (blockIdx.x * 256 + threadIdx.x) >> 5;
    int lane = threadIdx.x & 31;
    if (w >= MT * KT) return;
    int tm = w / KT, tk = w % KT;
    int row = tm * 16 + (lane >> 2);
    int kc  = tk * 16 + ((lane & 3) << 1);

    float2 v00 = *(const float2*)(X + (size_t)row * Cn + kc);
    float2 v10 = *(const float2*)(X + (size_t)(row + 8) * Cn + kc);
    float2 v01 = *(const float2*)(X + (size_t)row * Cn + kc + 8);
    float2 v11 = *(const float2*)(X + (size_t)(row + 8) * Cn + kc + 8);

    uint4 h, l;
    split2(v00.x, v00.y, h.x, l.x);
    split2(v10.x, v10.y, h.y, l.y);
    split2(v01.x, v01.y, h.z, l.z);
    split2(v11.x, v11.y, h.w, l.w);
    size_t o = (size_t)w * 32 + lane;
    dh[o] = h;
    dl[o] = l;
}

__global__ __launch_bounds__(256)
void split_w_kernel(const float* __restrict__ Wq, const float* __restrict__ Wk,
                    const float* __restrict__ Wv, const float* __restrict__ Wp)
{
    int w = (blockIdx.x * 256 + threadIdx.x) >> 5;
    int lane = threadIdx.x & 31;
    if (w >= 4 * NTW * KT) return;
    int mat = w / (NTW * KT);
    int rem = w % (NTW * KT);
    int tn = rem / KT, tk = rem % KT;

    const float* W;
    switch (mat) {
        case 0: W = Wq; break;
        case 1: W = Wk; break;
        case 2: W = Wv; break;
        default: W = Wp; break;
    }
    int n  = tn * 8 + (lane >> 2);
    int k0 = tk * 16 + ((lane & 3) << 1);

    float b00 = W[(size_t)k0 * Cn + n];
    float b01 = W[(size_t)(k0 + 1) * Cn + n];
    float b10 = W[(size_t)(k0 + 8) * Cn + n];
    float b11 = W[(size_t)(k0 + 9) * Cn + n];

    uint4 o;
    split2(b00, b01, o.x, o.z);
    split2(b10, b11, o.y, o.w);
    g_wf[(size_t)w * 32 + lane] = o;
}

// ---------------------------------------------------------------------------
// Attention-side split kernels: fp32 Q/K/V -> fragment-major bf16 hi/lo
// ---------------------------------------------------------------------------
__global__ __launch_bounds__(256)
void split_q_kernel()
{
    int wv = (blockIdx.x * 256 + threadIdx.x) >> 5;
    int lane = threadIdx.x & 31;
    if (wv >= BH * 64 * 4) return;
    int dc = wv & 3;
    int mt = (wv >> 2) & 63;
    int bh = wv >> 8;
    int b = bh / Hn, h = bh % Hn;
    int row = b * Tn + mt * 16 + (lane >> 2);
    int col = h * 64 + dc * 16 + ((lane & 3) << 1);
    const float* X = g_q;

    float2 v00 = *(const float2*)(X + (size_t)row * Cn + col);
    float2 v10 = *(const float2*)(X + (size_t)(row + 8) * Cn + col);
    float2 v01 = *(const float2*)(X + (size_t)row * Cn + col + 8);
    float2 v11 = *(const float2*)(X + (size_t)(row + 8) * Cn + col + 8);

    const float sc = 0.125f;  // 1/sqrt(64) folded into Q
    uint4 h4, l4;
    split2(sc * v00.x, sc * v00.y, h4.x, l4.x);
    split2(sc * v10.x, sc * v10.y, h4.y, l4.y);
    split2(sc * v01.x, sc * v01.y, h4.z, l4.z);
    split2(sc * v11.x, sc * v11.y, h4.w, l4.w);
    size_t o = (size_t)wv * 32 + lane;
    g_qfh[o] = h4;
    g_qfl[o] = l4;
}

__global__ __launch_bounds__(256)
void split_k_kernel()
{
    int wv = (blockIdx.x * 256 + threadIdx.x) >> 5;
    int lane = threadIdx.x & 31;
    if (wv >= BH * 128 * 4) return;
    int dc = wv & 3;
    int nt = (wv >> 2) & 127;
    int bh = wv >> 9;
    int b = bh / Hn, h = bh % Hn;
    int row = b * Tn + nt * 8 + (lane >> 2);
    int col = h * 64 + dc * 16 + ((lane & 3) << 1);

    float b00 = g_k[(size_t)row * Cn + col];
    float b01 = g_k[(size_t)row * Cn + col + 1];
    float b10 = g_k[(size_t)row * Cn + col + 8];
    float b11 = g_k[(size_t)row * Cn + col + 9];

    uint4 o;
    split2(b00, b01, o.x, o.z);
    split2(b10, b11, o.y, o.w);
    g_kf[(size_t)wv * 32 + lane] = o;
}

__global__ __launch_bounds__(256)
void split_v_kernel()
{
    int wv = (blockIdx.x * 256 + threadIdx.x) >> 5;
    int lane = threadIdx.x & 31;
    if (wv >= BH * 8 * 64) return;
    int kc = wv & 63;
    int dt = (wv >> 6) & 7;
    int bh = wv >> 9;
    int b = bh / Hn, h = bh % Hn;
    int k = kc * 16 + ((lane & 3) << 1);
    int d = dt * 8 + (lane >> 2);
    int row = b * Tn + k;
    int col = h * 64 + d;

    float b00 = g_v[(size_t)row * Cn + col];
    float b01 = g_v[(size_t)(row + 1) * Cn + col];
    float b10 = g_v[(size_t)(row + 8) * Cn + col];
    float b11 = g_v[(size_t)(row + 9) * Cn + col];

    uint4 o;
    split2(b00, b01, o.x, o.z);
    split2(b10, b11, o.y, o.w);
    g_vtf[(size_t)wv * 32 + lane] = o;
}

// ---------------------------------------------------------------------------
// bf16x3 tensor-core GEMM (unchanged from R3)
// ---------------------------------------------------------------------------
static constexpr int STG_BYTES = 16384;
static constexpr int GEMM_SMEM = 4 * STG_BYTES;

__device__ __forceinline__ void gemm_mma_body(const uint4* __restrict__ Ah,
                                              const uint4* __restrict__ Al,
                                              const uint4* __restrict__ Wf,
                                              const float* __restrict__ bias,
                                              float* __restrict__ Out)
{
    extern __shared__ __align__(16) char smem[];
    const uint32_t sbase = smem_u32(smem);
    const int tid  = threadIdx.x;
    const int lane = tid & 31;
    const int wid  = tid >> 5;
    const int wm   = wid >> 1;
    const int wn   = wid & 1;

    const int mtBase = blockIdx.y * 8;
    const int ntBase = blockIdx.x * 16;

    const int cp_mt   = tid >> 5;
    const int cp_lane = lane;

    const uint4* srcAh = Ah + ((size_t)(mtBase + cp_mt) * KT) * 32 + cp_lane;
    const uint4* srcAl = Al + ((size_t)(mtBase + cp_mt) * KT) * 32 + cp_lane;
    const uint4* srcB0 = Wf + ((size_t)(ntBase + cp_mt) * KT) * 32 + cp_lane;
    const uint4* srcB1 = Wf + ((size_t)(ntBase + cp_mt + 8) * KT) * 32 + cp_lane;

    const uint32_t dA0 = sbase + cp_mt * 512 + cp_lane * 16;
    const uint32_t dA1 = dA0 + 4096;
    const uint32_t dB0 = sbase + 8192 + cp_mt * 512 + cp_lane * 16;
    const uint32_t dB1 = dB0 + 8 * 512;

    float d[2][8][4];
#pragma unroll
    for (int i = 0; i < 2; i++)
#pragma unroll
        for (int j = 0; j < 8; j++)
#pragma unroll
            for (int e = 0; e < 4; e++) d[i][j][e] = 0.f;

    auto issue = [&](int slot, int tk) {
        uint32_t so = (uint32_t)slot * STG_BYTES;
        cp16(dA0 + so, srcAh + (size_t)tk * 32);
        cp16(dA1 + so, srcAl + (size_t)tk * 32);
        cp16(dB0 + so, srcB0 + (size_t)tk * 32);
        cp16(dB1 + so, srcB1 + (size_t)tk * 32);
    };

    issue(0, 0); CP_COMMIT();
    issue(1, 1); CP_COMMIT();
    issue(2, 2); CP_COMMIT();

    const char* sA = smem;
    for (int k = 0; k < KT; k++) {
        CP_WAIT2();
        __syncthreads();
        if (k + 3 < KT) issue((k + 3) & 3, k + 3);
        CP_COMMIT();

        const char* stg = sA + (size_t)(k & 3) * STG_BYTES;
        uint4 ah0 = *(const uint4*)(stg + (wm * 2 + 0) * 512 + lane * 16);
        uint4 ah1 = *(const uint4*)(stg + (wm * 2 + 1) * 512 + lane * 16);
        uint4 al0 = *(const uint4*)(stg + 4096 + (wm * 2 + 0) * 512 + lane * 16);
        uint4 al1 = *(const uint4*)(stg + 4096 + (wm * 2 + 1) * 512 + lane * 16);
#pragma unroll
        for (int nt = 0; nt < 8; nt++) {
            uint4 b = *(const uint4*)(stg + 8192 + (wn * 8 + nt) * 512 + lane * 16);
            mma16816(d[0][nt], (const uint32_t*)&ah0, b.x, b.y);
            mma16816(d[0][nt], (const uint32_t*)&ah0, b.z, b.w);
            mma16816(d[0][nt], (const uint32_t*)&al0, b.x, b.y);
            mma16816(d[1][nt], (const uint32_t*)&ah1, b.x, b.y);
            mma16816(d[1][nt], (const uint32_t*)&ah1, b.z, b.w);
            mma16816(d[1][nt], (const uint32_t*)&al1, b.x, b.y);
        }
    }

    const int rbase = blockIdx.y * 128 + wm * 32 + (lane >> 2);
    const int cb    = blockIdx.x * 128 + wn * 64 + ((lane & 3) << 1);
#pragma unroll
    for (int mt = 0; mt < 2; mt++) {
#pragma unroll
        for (int nt = 0; nt < 8; nt++) {
            int col = cb + nt * 8;
            float bx = bias[col], by = bias[col + 1];
            int r0 = rbase + mt * 16;
            float2 v0 = make_float2(d[mt][nt][0] + bx, d[mt][nt][1] + by);
            float2 v1 = make_float2(d[mt][nt][2] + bx, d[mt][nt][3] + by);
            *(float2*)(Out + (size_t)r0 * Cn + col) = v0;
            *(float2*)(Out + (size_t)(r0 + 8) * Cn + col) = v1;
        }
    }
}

__global__ __launch_bounds__(256, 1)
void qkv_mma(const float* __restrict__ bq, const float* __restrict__ bk,
             const float* __restrict__ bv)
{
    const uint4* Wf = g_wf + (size_t)blockIdx.z * NTW * KT * 32;
    const float* bb;
    float* Out;
    if (blockIdx.z == 0)      { bb = bq; Out = g_q; }
    else if (blockIdx.z == 1) { bb = bk; Out = g_k; }
    else                      { bb = bv; Out = g_v; }
    gemm_mma_body(g_xfh, g_xfl, Wf, bb, Out);
}

__global__ __launch_bounds__(256, 1)
void proj_mma(const float* __restrict__ bp, float* __restrict__ out)
{
    gemm_mma_body(g_yfh, g_yfl, g_wf + (size_t)3 * NTW * KT * 32, bp, out);
}

// ---------------------------------------------------------------------------
// Tensor-core flash attention.
// Block = (q-tile of 64 rows, head, batch), 128 threads = 4 warps (m16 each).
// 3-stage cp.async pipeline of 32KB K+V fragment tiles. bf16x3 everywhere.
// Stage layout: K frags [nt*4+dc][lane] (16KB), V frags at +16KB [dt*4+kc][lane].
// ---------------------------------------------------------------------------
static constexpr int ATT_STG  = 32768;
static constexpr int ATT_SMEM = 3 * ATT_STG;

__global__ __launch_bounds__(128, 1)
void attn_mma()
{
    extern __shared__ __align__(16) char smem[];
    const uint32_t sbase = smem_u32(smem);
    const int tid  = threadIdx.x;
    const int lane = tid & 31;
    const int w    = tid >> 5;
    const int qt   = blockIdx.x;
    const int h    = blockIdx.y;
    const int b    = blockIdx.z;
    const int bh   = b * Hn + h;
    const int nkt  = qt + 1;

    // Q fragments (hi/lo, 4 d-chunks), pre-scaled by 1/8
    uint4 qh[4], ql[4];
    {
        const uint4* Qh = g_qfh + ((size_t)(bh * 64 + qt * 4 + w) * 4) * 32 + lane;
        const uint4* Ql = g_qfl + ((size_t)(bh * 64 + qt * 4 + w) * 4) * 32 + lane;
#pragma unroll
        for (int dc = 0; dc < 4; dc++) { qh[dc] = Qh[dc * 32]; ql[dc] = Ql[dc * 32]; }
    }

    float o[8][4];
#pragma unroll
    for (int i = 0; i < 8; i++)
#pragma unroll
        for (int j = 0; j < 4; j++) o[i][j] = 0.f;
    float m[2] = {-1e30f, -1e30f}, l[2] = {0.f, 0.f};

    const uint4* Ksrc = g_kf  + (size_t)bh * 128 * 4 * 32;
    const uint4* Vsrc = g_vtf + (size_t)bh * 8 * 64 * 32;
    const int vkc = tid >> 5;  // 0..3 (kc slot this thread copies)

    auto issue = [&](int slot, int kt) {
        uint32_t so = sbase + (uint32_t)slot * ATT_STG;
        const uint4* ks = Ksrc + (size_t)kt * 1024;
#pragma unroll
        for (int i = 0; i < 8; i++)
            cp16(so + (uint32_t)(i * 128 + tid) * 16, ks + i * 128 + tid);
#pragma unroll
        for (int dt = 0; dt < 8; dt++)
            cp16(so + 16384 + (uint32_t)((dt * 4 + vkc) * 32 + lane) * 16,
                 Vsrc + ((size_t)dt * 64 + kt * 4 + vkc) * 32 + lane);
    };

    issue(0, 0); CP_COMMIT();
    if (nkt > 1) issue(1, 1);
    CP_COMMIT();

    for (int kt = 0; kt < nkt; kt++) {
        CP_WAIT1();
        __syncthreads();
        if (kt + 2 < nkt) issue((kt + 2) % 3, kt + 2);
        CP_COMMIT();

        const char* stK = smem + (size_t)(kt % 3) * ATT_STG;
        const char* stV = stK + 16384;

        // S = Q @ K^T (bf16x3)
        float s[8][4];
#pragma unroll
        for (int i = 0; i < 8; i++)
#pragma unroll
            for (int j = 0; j < 4; j++) s[i][j] = 0.f;
#pragma unroll
        for (int dc = 0; dc < 4; dc++) {
#pragma unroll
            for (int nt = 0; nt < 8; nt++) {
                uint4 kb4 = *(const uint4*)(stK + ((nt * 4 + dc) * 32 + lane) * 16);
                mma16816(s[nt], (const uint32_t*)&qh[dc], kb4.x, kb4.y);
                mma16816(s[nt], (const uint32_t*)&qh[dc], kb4.z, kb4.w);
                mma16816(s[nt], (const uint32_t*)&ql[dc], kb4.x, kb4.y);
            }
        }

        // Causal mask (diagonal tile only; scale already folded into Q)
        if (kt == qt) {
            int r0 = w * 16 + (lane >> 2);
            int c0 = (lane & 3) << 1;
#pragma unroll
            for (int nt = 0; nt < 8; nt++) {
                int col = nt * 8 + c0;
                if (col > r0)     s[nt][0] = -1e30f;
                if (col + 1 > r0) s[nt][1] = -1e30f;
                if (col > r0 + 8)     s[nt][2] = -1e30f;
                if (col + 1 > r0 + 8) s[nt][3] = -1e30f;
            }
        }

        // Online softmax per row-half
#pragma unroll
        for (int i = 0; i < 2; i++) {
            float tm = -1e30f;
#pragma unroll
            for (int nt = 0; nt < 8; nt++)
                tm = fmaxf(tm, fmaxf(s[nt][2 * i], s[nt][2 * i + 1]));
            tm = fmaxf(tm, __shfl_xor_sync(0xffffffffu, tm, 1));
            tm = fmaxf(tm, __shfl_xor_sync(0xffffffffu, tm, 2));
            float newm = fmaxf(m[i], tm);
            float fac  = __expf(m[i] - newm);
            m[i] = newm;
            float rs = 0.f;
#pragma unroll
            for (int nt = 0; nt < 8; nt++) {
                float p0 = __expf(s[nt][2 * i] - newm);
                float p1 = __expf(s[nt][2 * i + 1] - newm);
                s[nt][2 * i] = p0;
                s[nt][2 * i + 1] = p1;
                rs += p0 + p1;
            }
            rs += __shfl_xor_sync(0xffffffffu, rs, 1);
            rs += __shfl_xor_sync(0xffffffffu, rs, 2);
            l[i] = l[i] * fac + rs;
#pragma unroll
            for (int dt = 0; dt < 8; dt++) {
                o[dt][2 * i]     *= fac;
                o[dt][2 * i + 1] *= fac;
            }
        }

        // O += P @ V  (P re-packed from S accumulator regs, bf16x3)
#pragma unroll
        for (int t = 0; t < 4; t++) {
            uint32_t ph[4], pl[4];
            split2(s[2 * t][0],     s[2 * t][1],     ph[0], pl[0]);
            split2(s[2 * t][2],     s[2 * t][3],     ph[1], pl[1]);
            split2(s[2 * t + 1][0], s[2 * t + 1][1], ph[2], pl[2]);
            split2(s[2 * t + 1][2], s[2 * t + 1][3], ph[3], pl[3]);
#pragma unroll
            for (int dt = 0; dt < 8; dt++) {
                uint4 v4 = *(const uint4*)(stV + ((dt * 4 + t) * 32 + lane) * 16);
                mma16816(o[dt], ph, v4.x, v4.y);
                mma16816(o[dt], ph, v4.z, v4.w);
                mma16816(o[dt], pl, v4.x, v4.y);
            }
        }
    }

    // Epilogue: normalize and write fp32 y (head-merged layout)
    const float inv0 = 1.f / l[0];
    const float inv1 = 1.f / l[1];
    const int row  = b * Tn + qt * 64 + w * 16 + (lane >> 2);
    const int colb = h * 64 + ((lane & 3) << 1);
#pragma unroll
    for (int dt = 0; dt < 8; dt++) {
        *(float2*)(g_y + (size_t)row * Cn + colb + dt * 8) =
            make_float2(o[dt][0] * inv0, o[dt][1] * inv0);
        *(float2*)(g_y + (size_t)(row + 8) * Cn + colb + dt * 8) =
            make_float2(o[dt][2] * inv1, o[dt][3] * inv1);
    }
}

// ---------------------------------------------------------------------------
extern "C" void kernel_launch(void* const* d_in, const int* in_sizes, int n_in,
                              void* d_out, int out_size)
{
    const float* x  = (const float*)d_in[0];
    const float* Wq = (const float*)d_in[1];
    const float* bq = (const float*)d_in[2];
    const float* Wk = (const float*)d_in[3];
    const float* bk = (const float*)d_in[4];
    const float* Wv = (const float*)d_in[5];
    const float* bv = (const float*)d_in[6];
    const float* Wp = (const float*)d_in[7];
    const float* bp = (const float*)d_in[8];
    float* out = (float*)d_out;

    cudaFuncSetAttribute(qkv_mma, cudaFuncAttributeMaxDynamicSharedMemorySize, GEMM_SMEM);
    cudaFuncSetAttribute(proj_mma, cudaFuncAttributeMaxDynamicSharedMemorySize, GEMM_SMEM);
    cudaFuncSetAttribute(attn_mma, cudaFuncAttributeMaxDynamicSharedMemorySize, ATT_SMEM);

    uint4 *xfh, *xfl, *yfh, *yfl;
    cudaGetSymbolAddress((void**)&xfh, g_xfh);
    cudaGetSymbolAddress((void**)&xfl, g_xfl);
    cudaGetSymbolAddress((void**)&yfh, g_yfh);
    cudaGetSymbolAddress((void**)&yfl, g_yfl);
    float* yp;
    cudaGetSymbolAddress((void**)&yp, g_y);

    split_act_kernel<<<(MT * KT) / 8, 256>>>(x, xfh, xfl);
    split_w_kernel<<<(4 * NTW * KT) / 8, 256>>>(Wq, Wk, Wv, Wp);
    qkv_mma<<<dim3(Cn / 128, Mn / 128, 3), 256, GEMM_SMEM>>>(bq, bk, bv);
    split_q_kernel<<<(BH * 64 * 4) / 8, 256>>>();
    split_k_kernel<<<(BH * 128 * 4) / 8, 256>>>();
    split_v_kernel<<<(BH * 8 * 64) / 8, 256>>>();
    attn_mma<<<dim3(Tn / 64, Hn, Bn), 128, ATT_SMEM>>>();
    split_act_kernel<<<(MT * KT) / 8, 256>>>(yp, yfh, yfl);
    proj_mma<<<dim3(Cn / 128, Mn / 128, 1), 256, GEMM_SMEM>>>(bp, out);
}

// round 5
// speedup vs baseline: 4.4971x; 1.8727x over previous
#include <cuda_runtime.h>
#include <cuda_fp16.h>
#include <cstdint>

static constexpr int Bn = 8, Tn = 1024, Cn = 768, Hn = 12, Dn = 64;
static constexpr int Mn = Bn * Tn;      // 8192
static constexpr int KT = Cn / 16;      // 48 k16 chunks
static constexpr int MT = Mn / 16;      // 512 m16 tiles
static constexpr int NTW = Cn / 8;      // 96 n8 tiles per weight matrix
static constexpr int BH = Bn * Hn;      // 96

// ---------------------------------------------------------------------------
// Scratch device globals
// ---------------------------------------------------------------------------
__device__ float g_v[Mn * Cn];          // fp32 V (for transposed split)

// A fragments (fp16 hi/lo): [mt][tk][lane] -> uint4 (a0..a3)
__device__ uint4 g_xfh[MT * KT * 32];
__device__ uint4 g_xfl[MT * KT * 32];
__device__ uint4 g_yfh[MT * KT * 32];
__device__ uint4 g_yfl[MT * KT * 32];
// Weights B-frags (single fp16): [mat][nt][tk][lane] -> uint2 {b0,b1}
__device__ uint2 g_wf[4 * NTW * KT * 32];
// Q A-frags (hi/lo, pre-scaled 1/8): [bh][mt(64)][dc(4)][lane]
__device__ uint4 g_qfh[BH * 64 * 4 * 32];
__device__ uint4 g_qfl[BH * 64 * 4 * 32];
// K B-frags (single): [bh][nt(128)][dc(4)][lane]
__device__ uint2 g_kf[BH * 128 * 4 * 32];
// V^T B-frags (single): [bh][dt(8)][kc(64)][lane]
__device__ uint2 g_vtf[BH * 8 * 64 * 32];

// ---------------------------------------------------------------------------
// Helpers
// ---------------------------------------------------------------------------
__device__ __forceinline__ uint32_t smem_u32(const void* p) {
    uint32_t a;
    asm("{ .reg .u64 t; cvta.to.shared.u64 t, %1; cvt.u32.u64 %0, t; }"
        : "=r"(a) : "l"(p));
    return a;
}
__device__ __forceinline__ void cp16(uint32_t dst, const void* src) {
    asm volatile("cp.async.ca.shared.global [%0], [%1], 16;\n" :: "r"(dst), "l"(src));
}
__device__ __forceinline__ void cp8(uint32_t dst, const void* src) {
    asm volatile("cp.async.ca.shared.global [%0], [%1], 8;\n" :: "r"(dst), "l"(src));
}
#define CP_COMMIT() asm volatile("cp.async.commit_group;\n" ::: "memory")
#define CP_WAIT2()  asm volatile("cp.async.wait_group 2;\n" ::: "memory")
#define CP_WAIT1()  asm volatile("cp.async.wait_group 1;\n" ::: "memory")

__device__ __forceinline__ void mma16816(float* d, const uint32_t* a,
                                         uint32_t b0, uint32_t b1) {
    asm volatile(
        "mma.sync.aligned.m16n8k16.row.col.f32.f16.f16.f32 "
        "{%0,%1,%2,%3}, {%4,%5,%6,%7}, {%8,%9}, {%0,%1,%2,%3};\n"
        : "+f"(d[0]), "+f"(d[1]), "+f"(d[2]), "+f"(d[3])
        : "r"(a[0]), "r"(a[1]), "r"(a[2]), "r"(a[3]), "r"(b0), "r"(b1));
}

__device__ __forceinline__ uint32_t packh(float x, float y) {
    __half2 h = __floats2half2_rn(x, y);
    return *reinterpret_cast<uint32_t*>(&h);
}
__device__ __forceinline__ void split2h(float x, float y, uint32_t& h, uint32_t& l) {
    __half hx = __float2half_rn(x), hy = __float2half_rn(y);
    h = ((uint32_t)__half_as_ushort(hy) << 16) | (uint32_t)__half_as_ushort(hx);
    l = packh(x - __half2float(hx), y - __half2float(hy));
}

// ---------------------------------------------------------------------------
// x split: fp32 [Mn][Cn] -> fp16 hi/lo A-fragments
// ---------------------------------------------------------------------------
__global__ __launch_bounds__(256)
void split_act_kernel(const float* __restrict__ X)
{
    int w = (blockIdx.x * 256 + threadIdx.x) >> 5;
    int lane = threadIdx.x & 31;
    if (w >= MT * KT) return;
    int tm = w / KT, tk = w % KT;
    int row = tm * 16 + (lane >> 2);
    int kc  = tk * 16 + ((lane & 3) << 1);

    float2 v00 = *(const float2*)(X + (size_t)row * Cn + kc);
    float2 v10 = *(const float2*)(X + (size_t)(row + 8) * Cn + kc);
    float2 v01 = *(const float2*)(X + (size_t)row * Cn + kc + 8);
    float2 v11 = *(const float2*)(X + (size_t)(row + 8) * Cn + kc + 8);

    uint4 h, l;
    split2h(v00.x, v00.y, h.x, l.x);
    split2h(v10.x, v10.y, h.y, l.y);
    split2h(v01.x, v01.y, h.z, l.z);
    split2h(v11.x, v11.y, h.w, l.w);
    size_t o = (size_t)w * 32 + lane;
    g_xfh[o] = h;
    g_xfl[o] = l;
}

// ---------------------------------------------------------------------------
// Weight split: fp32 W[k][n] -> single fp16 B-fragments
// ---------------------------------------------------------------------------
__global__ __launch_bounds__(256)
void split_w_kernel(const float* __restrict__ Wq, const float* __restrict__ Wk,
                    const float* __restrict__ Wv, const float* __restrict__ Wp)
{
    int w = (blockIdx.x * 256 + threadIdx.x) >> 5;
    int lane = threadIdx.x & 31;
    if (w >= 4 * NTW * KT) return;
    int mat = w / (NTW * KT);
    int rem = w % (NTW * KT);
    int tn = rem / KT, tk = rem % KT;

    const float* W;
    switch (mat) {
        case 0: W = Wq; break;
        case 1: W = Wk; break;
        case 2: W = Wv; break;
        default: W = Wp; break;
    }
    int n  = tn * 8 + (lane >> 2);
    int k0 = tk * 16 + ((lane & 3) << 1);

    uint2 o;
    o.x = packh(W[(size_t)k0 * Cn + n], W[(size_t)(k0 + 1) * Cn + n]);
    o.y = packh(W[(size_t)(k0 + 8) * Cn + n], W[(size_t)(k0 + 9) * Cn + n]);
    g_wf[(size_t)w * 32 + lane] = o;
}

// ---------------------------------------------------------------------------
// V split: fp32 g_v -> transposed single fp16 B-fragments (n=d, k=key)
// ---------------------------------------------------------------------------
__global__ __launch_bounds__(256)
void split_v_kernel()
{
    int wv = (blockIdx.x * 256 + threadIdx.x) >> 5;
    int lane = threadIdx.x & 31;
    if (wv >= BH * 8 * 64) return;
    int kc = wv & 63;
    int dt = (wv >> 6) & 7;
    int bh = wv >> 9;
    int b = bh / Hn, h = bh % Hn;
    int k = kc * 16 + ((lane & 3) << 1);
    int d = dt * 8 + (lane >> 2);
    int row = b * Tn + k;
    int col = h * 64 + d;

    uint2 o;
    o.x = packh(g_v[(size_t)row * Cn + col], g_v[(size_t)(row + 1) * Cn + col]);
    o.y = packh(g_v[(size_t)(row + 8) * Cn + col], g_v[(size_t)(row + 9) * Cn + col]);
    g_vtf[(size_t)wv * 32 + lane] = o;
}

// ---------------------------------------------------------------------------
// fp16 (A-split) tensor-core GEMM: Out tile = A[128,768] @ W[768,128] + bias
// 256 threads (8 warps: 4m x 2n). 4-stage cp.async pipeline, 12KB/stage.
// Epilogue modes: 0 = fp32 (+bias) to Out; 1 = Q A-frags; 2 = K B-frags.
// ---------------------------------------------------------------------------
static constexpr int STG_BYTES = 12288;
static constexpr int GEMM_SMEM = 4 * STG_BYTES;   // 48KB

__device__ __forceinline__ void gemm_mma_body(const uint4* __restrict__ Ah,
                                              const uint4* __restrict__ Al,
                                              const uint2* __restrict__ Wf,
                                              const float* __restrict__ bias,
                                              float* __restrict__ Out,
                                              int mode)
{
    extern __shared__ __align__(16) char smem[];
    const uint32_t sbase = smem_u32(smem);
    const int tid  = threadIdx.x;
    const int lane = tid & 31;
    const int wid  = tid >> 5;
    const int wm   = wid >> 1;
    const int wn   = wid & 1;

    const int mtBase = blockIdx.y * 8;
    const int ntBase = blockIdx.x * 16;
    const int cp_t   = wid;   // 0..7

    const uint4* srcAh = Ah + ((size_t)(mtBase + cp_t) * KT) * 32 + lane;
    const uint4* srcAl = Al + ((size_t)(mtBase + cp_t) * KT) * 32 + lane;
    const uint2* srcB0 = Wf + ((size_t)(ntBase + cp_t) * KT) * 32 + lane;
    const uint2* srcB1 = Wf + ((size_t)(ntBase + cp_t + 8) * KT) * 32 + lane;

    const uint32_t dA0 = sbase + cp_t * 512 + lane * 16;
    const uint32_t dA1 = dA0 + 4096;
    const uint32_t dB0 = sbase + 8192 + cp_t * 256 + lane * 8;
    const uint32_t dB1 = dB0 + 2048;

    float d[2][8][4];
#pragma unroll
    for (int i = 0; i < 2; i++)
#pragma unroll
        for (int j = 0; j < 8; j++)
#pragma unroll
            for (int e = 0; e < 4; e++) d[i][j][e] = 0.f;

    auto issue = [&](int slot, int tk) {
        uint32_t so = (uint32_t)slot * STG_BYTES;
        cp16(dA0 + so, srcAh + (size_t)tk * 32);
        cp16(dA1 + so, srcAl + (size_t)tk * 32);
        cp8(dB0 + so, srcB0 + (size_t)tk * 32);
        cp8(dB1 + so, srcB1 + (size_t)tk * 32);
    };

    issue(0, 0); CP_COMMIT();
    issue(1, 1); CP_COMMIT();
    issue(2, 2); CP_COMMIT();

    for (int k = 0; k < KT; k++) {
        CP_WAIT2();
        __syncthreads();
        if (k + 3 < KT) issue((k + 3) & 3, k + 3);
        CP_COMMIT();

        const char* stg = smem + (size_t)(k & 3) * STG_BYTES;
        uint4 ah0 = *(const uint4*)(stg + (wm * 2 + 0) * 512 + lane * 16);
        uint4 ah1 = *(const uint4*)(stg + (wm * 2 + 1) * 512 + lane * 16);
        uint4 al0 = *(const uint4*)(stg + 4096 + (wm * 2 + 0) * 512 + lane * 16);
        uint4 al1 = *(const uint4*)(stg + 4096 + (wm * 2 + 1) * 512 + lane * 16);
#pragma unroll
        for (int nt = 0; nt < 8; nt++) {
            uint2 b = *(const uint2*)(stg + 8192 + (wn * 8 + nt) * 256 + lane * 8);
            mma16816(d[0][nt], (const uint32_t*)&ah0, b.x, b.y);
            mma16816(d[0][nt], (const uint32_t*)&al0, b.x, b.y);
            mma16816(d[1][nt], (const uint32_t*)&ah1, b.x, b.y);
            mma16816(d[1][nt], (const uint32_t*)&al1, b.x, b.y);
        }
    }

    const int cb = blockIdx.x * 128 + wn * 64 + ((lane & 3) << 1);
    const int h  = blockIdx.x * 2 + wn;   // head for modes 1/2

#pragma unroll
    for (int mt = 0; mt < 2; mt++) {
        const int rg = blockIdx.y * 128 + wm * 32 + mt * 16;   // tile row base
        if (mode == 0) {
            const int r0 = rg + (lane >> 2);
#pragma unroll
            for (int nt = 0; nt < 8; nt++) {
                int col = cb + nt * 8;
                float bx = bias[col], by = bias[col + 1];
                *(float2*)(Out + (size_t)r0 * Cn + col) =
                    make_float2(d[mt][nt][0] + bx, d[mt][nt][1] + by);
                *(float2*)(Out + (size_t)(r0 + 8) * Cn + col) =
                    make_float2(d[mt][nt][2] + bx, d[mt][nt][3] + by);
            }
        } else if (mode == 1) {
            // Q A-fragments: scale 1/8, bias folded
            const int bq_ = rg >> 10;
            const int mtq = (rg & 1023) >> 4;
            const size_t base =
                ((size_t)((bq_ * Hn + h) * 64 + mtq) * 4) * 32 + lane;
#pragma unroll
            for (int dc = 0; dc < 4; dc++) {
                int c0 = cb + (2 * dc) * 8, c1 = cb + (2 * dc + 1) * 8;
                float b00 = bias[c0], b01 = bias[c0 + 1];
                float b10 = bias[c1], b11 = bias[c1 + 1];
                uint4 hh, ll;
                split2h((d[mt][2*dc][0]   + b00) * 0.125f,
                        (d[mt][2*dc][1]   + b01) * 0.125f, hh.x, ll.x);
                split2h((d[mt][2*dc][2]   + b00) * 0.125f,
                        (d[mt][2*dc][3]   + b01) * 0.125f, hh.y, ll.y);
                split2h((d[mt][2*dc+1][0] + b10) * 0.125f,
                        (d[mt][2*dc+1][1] + b11) * 0.125f, hh.z, ll.z);
                split2h((d[mt][2*dc+1][2] + b10) * 0.125f,
                        (d[mt][2*dc+1][3] + b11) * 0.125f, hh.w, ll.w);
                g_qfh[base + dc * 32] = hh;
                g_qfl[base + dc * 32] = ll;
            }
        } else {
            // K B-fragments (single fp16): two n8 key-tiles per m16
            const int bq_ = rg >> 10;
            const int ntk = (rg & 1023) >> 3;
            const size_t base =
                ((size_t)((bq_ * Hn + h) * 128 + ntk) * 4) * 32 + lane;
#pragma unroll
            for (int dc = 0; dc < 4; dc++) {
                int c0 = cb + (2 * dc) * 8, c1 = cb + (2 * dc + 1) * 8;
                float b00 = bias[c0], b01 = bias[c0 + 1];
                float b10 = bias[c1], b11 = bias[c1 + 1];
                uint2 t0, t1;
                t0.x = packh(d[mt][2*dc][0]   + b00, d[mt][2*dc][1]   + b01);
                t0.y = packh(d[mt][2*dc+1][0] + b10, d[mt][2*dc+1][1] + b11);
                t1.x = packh(d[mt][2*dc][2]   + b00, d[mt][2*dc][3]   + b01);
                t1.y = packh(d[mt][2*dc+1][2] + b10, d[mt][2*dc+1][3] + b11);
                g_kf[base + dc * 32]            = t0;
                g_kf[base + 4 * 32 + dc * 32]   = t1;
            }
        }
    }
}

__global__ __launch_bounds__(256, 1)
void qkv_mma(const float* __restrict__ bq, const float* __restrict__ bk,
             const float* __restrict__ bv)
{
    const uint2* Wf = g_wf + (size_t)blockIdx.z * NTW * KT * 32;
    if (blockIdx.z == 0)      gemm_mma_body(g_xfh, g_xfl, Wf, bq, nullptr, 1);
    else if (blockIdx.z == 1) gemm_mma_body(g_xfh, g_xfl, Wf, bk, nullptr, 2);
    else                      gemm_mma_body(g_xfh, g_xfl, Wf, bv, g_v, 0);
}

__global__ __launch_bounds__(256, 1)
void proj_mma(const float* __restrict__ bp, float* __restrict__ out)
{
    gemm_mma_body(g_yfh, g_yfl, g_wf + (size_t)3 * NTW * KT * 32, bp, out, 0);
}

// ---------------------------------------------------------------------------
// fp16 tensor-core flash attention.
// Block = (64 q-rows, head, batch), 128 threads = 4 warps (m16 each).
// 3-stage cp.async pipeline of 16KB K+V single-fp16 fragment tiles.
// Q split hi/lo (2 MMAs per S step), P single fp16 (1 MMA per PV step).
// Epilogue writes y A-fragments (hi/lo) directly for the proj GEMM.
// ---------------------------------------------------------------------------
static constexpr int ATT_STG  = 16384;
static constexpr int ATT_SMEM = 3 * ATT_STG;   // 48KB

__global__ __launch_bounds__(128, 1)
void attn_mma()
{
    extern __shared__ __align__(16) char smem[];
    const uint32_t sbase = smem_u32(smem);
    const int tid  = threadIdx.x;
    const int lane = tid & 31;
    const int w    = tid >> 5;
    const int qt   = blockIdx.x;
    const int h    = blockIdx.y;
    const int b    = blockIdx.z;
    const int bh   = b * Hn + h;
    const int nkt  = qt + 1;

    // Q fragments (hi/lo fp16, pre-scaled 1/8)
    uint4 qh[4], ql[4];
    {
        const uint4* Qh = g_qfh + ((size_t)(bh * 64 + qt * 4 + w) * 4) * 32 + lane;
        const uint4* Ql = g_qfl + ((size_t)(bh * 64 + qt * 4 + w) * 4) * 32 + lane;
#pragma unroll
        for (int dc = 0; dc < 4; dc++) { qh[dc] = Qh[dc * 32]; ql[dc] = Ql[dc * 32]; }
    }

    float o[8][4];
#pragma unroll
    for (int i = 0; i < 8; i++)
#pragma unroll
        for (int j = 0; j < 4; j++) o[i][j] = 0.f;
    float m[2] = {-1e30f, -1e30f}, l[2] = {0.f, 0.f};

    const uint2* Ksrc = g_kf  + (size_t)bh * 128 * 4 * 32;
    const uint2* Vsrc = g_vtf + (size_t)bh * 8 * 64 * 32;
    const int vkc = w;  // kc slot this warp copies

    auto issue = [&](int slot, int kt) {
        uint32_t so = sbase + (uint32_t)slot * ATT_STG;
        const uint2* ks = Ksrc + (size_t)kt * 1024;
#pragma unroll
        for (int i = 0; i < 8; i++)
            cp8(so + (uint32_t)(i * 128 + tid) * 8, ks + i * 128 + tid);
#pragma unroll
        for (int dt = 0; dt < 8; dt++)
            cp8(so + 8192 + (uint32_t)((dt * 4 + vkc) * 32 + lane) * 8,
                Vsrc + ((size_t)dt * 64 + kt * 4 + vkc) * 32 + lane);
    };

    issue(0, 0); CP_COMMIT();
    if (nkt > 1) issue(1, 1);
    CP_COMMIT();

    for (int kt = 0; kt < nkt; kt++) {
        CP_WAIT1();
        __syncthreads();
        if (kt + 2 < nkt) issue((kt + 2) % 3, kt + 2);
        CP_COMMIT();

        const char* stK = smem + (size_t)(kt % 3) * ATT_STG;
        const char* stV = stK + 8192;

        // S = Q @ K^T (Q split, K single)
        float s[8][4];
#pragma unroll
        for (int i = 0; i < 8; i++)
#pragma unroll
            for (int j = 0; j < 4; j++) s[i][j] = 0.f;
#pragma unroll
        for (int dc = 0; dc < 4; dc++) {
#pragma unroll
            for (int nt = 0; nt < 8; nt++) {
                uint2 kb = *(const uint2*)(stK + ((nt * 4 + dc) * 32 + lane) * 8);
                mma16816(s[nt], (const uint32_t*)&qh[dc], kb.x, kb.y);
                mma16816(s[nt], (const uint32_t*)&ql[dc], kb.x, kb.y);
            }
        }

        // Causal mask (diagonal tile only)
        if (kt == qt) {
            int r0 = w * 16 + (lane >> 2);
            int c0 = (lane & 3) << 1;
#pragma unroll
            for (int nt = 0; nt < 8; nt++) {
                int col = nt * 8 + c0;
                if (col > r0)         s[nt][0] = -1e30f;
                if (col + 1 > r0)     s[nt][1] = -1e30f;
                if (col > r0 + 8)     s[nt][2] = -1e30f;
                if (col + 1 > r0 + 8) s[nt][3] = -1e30f;
            }
        }

        // Online softmax per row-half
#pragma unroll
        for (int i = 0; i < 2; i++) {
            float tm = -1e30f;
#pragma unroll
            for (int nt = 0; nt < 8; nt++)
                tm = fmaxf(tm, fmaxf(s[nt][2 * i], s[nt][2 * i + 1]));
            tm = fmaxf(tm, __shfl_xor_sync(0xffffffffu, tm, 1));
            tm = fmaxf(tm, __shfl_xor_sync(0xffffffffu, tm, 2));
            float newm = fmaxf(m[i], tm);
            float fac  = __expf(m[i] - newm);
            m[i] = newm;
            float rs = 0.f;
#pragma unroll
            for (int nt = 0; nt < 8; nt++) {
                float p0 = __expf(s[nt][2 * i] - newm);
                float p1 = __expf(s[nt][2 * i + 1] - newm);
                s[nt][2 * i] = p0;
                s[nt][2 * i + 1] = p1;
                rs += p0 + p1;
            }
            rs += __shfl_xor_sync(0xffffffffu, rs, 1);
            rs += __shfl_xor_sync(0xffffffffu, rs, 2);
            l[i] = l[i] * fac + rs;
#pragma unroll
            for (int dt = 0; dt < 8; dt++) {
                o[dt][2 * i]     *= fac;
                o[dt][2 * i + 1] *= fac;
            }
        }

        // O += P @ V  (P single fp16, re-packed from S accumulators)
#pragma unroll
        for (int t = 0; t < 4; t++) {
            uint32_t ph[4];
            ph[0] = packh(s[2*t][0],   s[2*t][1]);
            ph[1] = packh(s[2*t][2],   s[2*t][3]);
            ph[2] = packh(s[2*t+1][0], s[2*t+1][1]);
            ph[3] = packh(s[2*t+1][2], s[2*t+1][3]);
#pragma unroll
            for (int dt = 0; dt < 8; dt++) {
                uint2 v = *(const uint2*)(stV + ((dt * 4 + t) * 32 + lane) * 8);
                mma16816(o[dt], ph, v.x, v.y);
            }
        }
    }

    // Epilogue: normalize, write y A-fragments (hi/lo) for proj GEMM
    const float inv0 = 1.f / l[0];
    const float inv1 = 1.f / l[1];
    const int mtg = b * 64 + qt * 4 + w;
#pragma unroll
    for (int dtc = 0; dtc < 4; dtc++) {
        uint4 hh, ll;
        split2h(o[2*dtc][0]   * inv0, o[2*dtc][1]   * inv0, hh.x, ll.x);
        split2h(o[2*dtc][2]   * inv1, o[2*dtc][3]   * inv1, hh.y, ll.y);
        split2h(o[2*dtc+1][0] * inv0, o[2*dtc+1][1] * inv0, hh.z, ll.z);
        split2h(o[2*dtc+1][2] * inv1, o[2*dtc+1][3] * inv1, hh.w, ll.w);
        size_t idx = ((size_t)mtg * KT + h * 4 + dtc) * 32 + lane;
        g_yfh[idx] = hh;
        g_yfl[idx] = ll;
    }
}

// ---------------------------------------------------------------------------
extern "C" void kernel_launch(void* const* d_in, const int* in_sizes, int n_in,
                              void* d_out, int out_size)
{
    const float* x  = (const float*)d_in[0];
    const float* Wq = (const float*)d_in[1];
    const float* bq = (const float*)d_in[2];
    const float* Wk = (const float*)d_in[3];
    const float* bk = (const float*)d_in[4];
    const float* Wv = (const float*)d_in[5];
    const float* bv = (const float*)d_in[6];
    const float* Wp = (const float*)d_in[7];
    const float* bp = (const float*)d_in[8];
    float* out = (float*)d_out;

    cudaFuncSetAttribute(qkv_mma, cudaFuncAttributeMaxDynamicSharedMemorySize, GEMM_SMEM);
    cudaFuncSetAttribute(proj_mma, cudaFuncAttributeMaxDynamicSharedMemorySize, GEMM_SMEM);
    cudaFuncSetAttribute(attn_mma, cudaFuncAttributeMaxDynamicSharedMemorySize, ATT_SMEM);

    split_act_kernel<<<(MT * KT) / 8, 256>>>(x);
    split_w_kernel<<<(4 * NTW * KT) / 8, 256>>>(Wq, Wk, Wv, Wp);
    qkv_mma<<<dim3(Cn / 128, Mn / 128, 3), 256, GEMM_SMEM>>>(bq, bk, bv);
    split_v_kernel<<<(BH * 8 * 64) / 8, 256>>>();
    attn_mma<<<dim3(Tn / 64, Hn, Bn), 128, ATT_SMEM>>>();
    proj_mma<<<dim3(Cn / 128, Mn / 128, 1), 256, GEMM_SMEM>>>(bp, out);
}

// round 6
// speedup vs baseline: 4.6713x; 1.0387x over previous
#include <cuda_runtime.h>
#include <cuda_fp16.h>
#include <cstdint>

static constexpr int Bn = 8, Tn = 1024, Cn = 768, Hn = 12, Dn = 64;
static constexpr int Mn = Bn * Tn;      // 8192
static constexpr int KT = Cn / 16;      // 48 k16 chunks
static constexpr int MT = Mn / 16;      // 512 m16 tiles
static constexpr int NTW = Cn / 8;      // 96 n8 tiles per weight matrix
static constexpr int BH = Bn * Hn;      // 96

// ---------------------------------------------------------------------------
// Scratch device globals
// ---------------------------------------------------------------------------
// A fragments (fp16 hi/lo): [mt][tk][lane] -> uint4 (a0..a3)
__device__ uint4 g_xfh[MT * KT * 32];
__device__ uint4 g_xfl[MT * KT * 32];
__device__ uint4 g_yfh[MT * KT * 32];
__device__ uint4 g_yfl[MT * KT * 32];
// Weights B-frags (single fp16): [mat][nt][tk][lane] -> uint2 {b0,b1}
__device__ uint2 g_wf[4 * NTW * KT * 32];
// Q A-frags (hi/lo, pre-scaled 1/8): [bh][mt(64)][dc(4)][lane]
__device__ uint4 g_qfh[BH * 64 * 4 * 32];
__device__ uint4 g_qfl[BH * 64 * 4 * 32];
// K B-frags (single): [bh][nt(128)][dc(4)][lane]
__device__ uint2 g_kf[BH * 128 * 4 * 32];
// V^T B-frags (single): [bh][dt(8)][kc(64)][lane]
__device__ uint2 g_vtf[BH * 8 * 64 * 32];

// ---------------------------------------------------------------------------
// Helpers
// ---------------------------------------------------------------------------
__device__ __forceinline__ uint32_t smem_u32(const void* p) {
    uint32_t a;
    asm("{ .reg .u64 t; cvta.to.shared.u64 t, %1; cvt.u32.u64 %0, t; }"
        : "=r"(a) : "l"(p));
    return a;
}
__device__ __forceinline__ void cp16(uint32_t dst, const void* src) {
    asm volatile("cp.async.ca.shared.global [%0], [%1], 16;\n" :: "r"(dst), "l"(src));
}
__device__ __forceinline__ void cp8(uint32_t dst, const void* src) {
    asm volatile("cp.async.ca.shared.global [%0], [%1], 8;\n" :: "r"(dst), "l"(src));
}
#define CP_COMMIT() asm volatile("cp.async.commit_group;\n" ::: "memory")
#define CP_WAIT2()  asm volatile("cp.async.wait_group 2;\n" ::: "memory")
#define CP_WAIT1()  asm volatile("cp.async.wait_group 1;\n" ::: "memory")

__device__ __forceinline__ void mma16816(float* d, const uint32_t* a,
                                         uint32_t b0, uint32_t b1) {
    asm volatile(
        "mma.sync.aligned.m16n8k16.row.col.f32.f16.f16.f32 "
        "{%0,%1,%2,%3}, {%4,%5,%6,%7}, {%8,%9}, {%0,%1,%2,%3};\n"
        : "+f"(d[0]), "+f"(d[1]), "+f"(d[2]), "+f"(d[3])
        : "r"(a[0]), "r"(a[1]), "r"(a[2]), "r"(a[3]), "r"(b0), "r"(b1));
}

__device__ __forceinline__ uint32_t packh(float x, float y) {
    __half2 h = __floats2half2_rn(x, y);
    return *reinterpret_cast<uint32_t*>(&h);
}
__device__ __forceinline__ void split2h(float x, float y, uint32_t& h, uint32_t& l) {
    __half hx = __float2half_rn(x), hy = __float2half_rn(y);
    h = ((uint32_t)__half_as_ushort(hy) << 16) | (uint32_t)__half_as_ushort(hx);
    l = packh(x - __half2float(hx), y - __half2float(hy));
}

// ---------------------------------------------------------------------------
// Combined input split: x -> A-frags (hi/lo); W -> single fp16 B-frags
// ---------------------------------------------------------------------------
static constexpr int ACT_BLKS = (MT * KT) / 8;          // 3072
static constexpr int W_BLKS   = (4 * NTW * KT) / 8;     // 2304

__global__ __launch_bounds__(256)
void split_xw_kernel(const float* __restrict__ X,
                     const float* __restrict__ Wq, const float* __restrict__ Wk,
                     const float* __restrict__ Wv, const float* __restrict__ Wp)
{
    int lane = threadIdx.x & 31;
    if (blockIdx.x < ACT_BLKS) {
        int w = (blockIdx.x * 256 + threadIdx.x) >> 5;
        int tm = w / KT, tk = w % KT;
        int row = tm * 16 + (lane >> 2);
        int kc  = tk * 16 + ((lane & 3) << 1);

        float2 v00 = *(const float2*)(X + (size_t)row * Cn + kc);
        float2 v10 = *(const float2*)(X + (size_t)(row + 8) * Cn + kc);
        float2 v01 = *(const float2*)(X + (size_t)row * Cn + kc + 8);
        float2 v11 = *(const float2*)(X + (size_t)(row + 8) * Cn + kc + 8);

        uint4 h, l;
        split2h(v00.x, v00.y, h.x, l.x);
        split2h(v10.x, v10.y, h.y, l.y);
        split2h(v01.x, v01.y, h.z, l.z);
        split2h(v11.x, v11.y, h.w, l.w);
        size_t o = (size_t)w * 32 + lane;
        g_xfh[o] = h;
        g_xfl[o] = l;
    } else {
        int w = ((blockIdx.x - ACT_BLKS) * 256 + threadIdx.x) >> 5;
        int mat = w / (NTW * KT);
        int rem = w % (NTW * KT);
        int tn = rem / KT, tk = rem % KT;

        const float* W;
        switch (mat) {
            case 0: W = Wq; break;
            case 1: W = Wk; break;
            case 2: W = Wv; break;
            default: W = Wp; break;
        }
        int n  = tn * 8 + (lane >> 2);
        int k0 = tk * 16 + ((lane & 3) << 1);

        uint2 o;
        o.x = packh(W[(size_t)k0 * Cn + n], W[(size_t)(k0 + 1) * Cn + n]);
        o.y = packh(W[(size_t)(k0 + 8) * Cn + n], W[(size_t)(k0 + 9) * Cn + n]);
        g_wf[(size_t)w * 32 + lane] = o;
    }
}

// ---------------------------------------------------------------------------
// fp16 (A-split) tensor-core GEMM: Out tile = A[128,768] @ W[768,128] + bias
// 256 threads (8 warps: 4m x 2n). 4-stage cp.async pipeline, 12KB/stage.
// Epilogue modes: 0 = fp32 (+bias) to Out; 1 = Q A-frags; 2 = K B-frags;
//                 3 = V^T B-frags via smem fp16 transpose (136-half stride).
// ---------------------------------------------------------------------------
static constexpr int STG_BYTES = 12288;
static constexpr int GEMM_SMEM = 4 * STG_BYTES;   // 48KB (transpose needs 34816B)

__device__ __forceinline__ void gemm_mma_body(const uint4* __restrict__ Ah,
                                              const uint4* __restrict__ Al,
                                              const uint2* __restrict__ Wf,
                                              const float* __restrict__ bias,
                                              float* __restrict__ Out,
                                              int mode)
{
    extern __shared__ __align__(16) char smem[];
    const uint32_t sbase = smem_u32(smem);
    const int tid  = threadIdx.x;
    const int lane = tid & 31;
    const int wid  = tid >> 5;
    const int wm   = wid >> 1;
    const int wn   = wid & 1;

    const int mtBase = blockIdx.y * 8;
    const int ntBase = blockIdx.x * 16;
    const int cp_t   = wid;

    const uint4* srcAh = Ah + ((size_t)(mtBase + cp_t) * KT) * 32 + lane;
    const uint4* srcAl = Al + ((size_t)(mtBase + cp_t) * KT) * 32 + lane;
    const uint2* srcB0 = Wf + ((size_t)(ntBase + cp_t) * KT) * 32 + lane;
    const uint2* srcB1 = Wf + ((size_t)(ntBase + cp_t + 8) * KT) * 32 + lane;

    const uint32_t dA0 = sbase + cp_t * 512 + lane * 16;
    const uint32_t dA1 = dA0 + 4096;
    const uint32_t dB0 = sbase + 8192 + cp_t * 256 + lane * 8;
    const uint32_t dB1 = dB0 + 2048;

    float d[2][8][4];
#pragma unroll
    for (int i = 0; i < 2; i++)
#pragma unroll
        for (int j = 0; j < 8; j++)
#pragma unroll
            for (int e = 0; e < 4; e++) d[i][j][e] = 0.f;

    auto issue = [&](int slot, int tk) {
        uint32_t so = (uint32_t)slot * STG_BYTES;
        cp16(dA0 + so, srcAh + (size_t)tk * 32);
        cp16(dA1 + so, srcAl + (size_t)tk * 32);
        cp8(dB0 + so, srcB0 + (size_t)tk * 32);
        cp8(dB1 + so, srcB1 + (size_t)tk * 32);
    };

    issue(0, 0); CP_COMMIT();
    issue(1, 1); CP_COMMIT();
    issue(2, 2); CP_COMMIT();

    for (int k = 0; k < KT; k++) {
        CP_WAIT2();
        __syncthreads();
        if (k + 3 < KT) issue((k + 3) & 3, k + 3);
        CP_COMMIT();

        const char* stg = smem + (size_t)(k & 3) * STG_BYTES;
        uint4 ah0 = *(const uint4*)(stg + (wm * 2 + 0) * 512 + lane * 16);
        uint4 ah1 = *(const uint4*)(stg + (wm * 2 + 1) * 512 + lane * 16);
        uint4 al0 = *(const uint4*)(stg + 4096 + (wm * 2 + 0) * 512 + lane * 16);
        uint4 al1 = *(const uint4*)(stg + 4096 + (wm * 2 + 1) * 512 + lane * 16);
#pragma unroll
        for (int nt = 0; nt < 8; nt++) {
            uint2 b = *(const uint2*)(stg + 8192 + (wn * 8 + nt) * 256 + lane * 8);
            mma16816(d[0][nt], (const uint32_t*)&ah0, b.x, b.y);
            mma16816(d[0][nt], (const uint32_t*)&al0, b.x, b.y);
            mma16816(d[1][nt], (const uint32_t*)&ah1, b.x, b.y);
            mma16816(d[1][nt], (const uint32_t*)&al1, b.x, b.y);
        }
    }

    const int cb = blockIdx.x * 128 + wn * 64 + ((lane & 3) << 1);
    const int h  = blockIdx.x * 2 + wn;

    if (mode == 3) {
        // V^T fragments via smem fp16 transpose (row stride 136 halves).
        __syncthreads();  // pipeline smem no longer needed
        __half* sv = reinterpret_cast<__half*>(smem);
#pragma unroll
        for (int mt = 0; mt < 2; mt++) {
            int r = wm * 32 + mt * 16 + (lane >> 2);
#pragma unroll
            for (int nt = 0; nt < 8; nt++) {
                int cl  = wn * 64 + nt * 8 + ((lane & 3) << 1);
                int col = blockIdx.x * 128 + cl;
                float bx = bias[col], by = bias[col + 1];
                *(__half2*)&sv[r * 136 + cl] =
                    __floats2half2_rn(d[mt][nt][0] + bx, d[mt][nt][1] + by);
                *(__half2*)&sv[(r + 8) * 136 + cl] =
                    __floats2half2_rn(d[mt][nt][2] + bx, d[mt][nt][3] + by);
            }
        }
        __syncthreads();
        const ushort* su = reinterpret_cast<const ushort*>(sv);
        const int bb  = blockIdx.y >> 3;
        const int kcb = (blockIdx.y & 7) * 8;
        const int dt  = wid;
#pragma unroll
        for (int hh = 0; hh < 2; hh++) {
            int dl  = hh * 64 + dt * 8 + (lane >> 2);
            int bh2 = bb * Hn + blockIdx.x * 2 + hh;
#pragma unroll
            for (int kl = 0; kl < 8; kl++) {
                int k0 = kl * 16 + ((lane & 3) << 1);
                uint2 o;
                o.x = (uint32_t)su[k0 * 136 + dl] |
                      ((uint32_t)su[(k0 + 1) * 136 + dl] << 16);
                o.y = (uint32_t)su[(k0 + 8) * 136 + dl] |
                      ((uint32_t)su[(k0 + 9) * 136 + dl] << 16);
                g_vtf[(((size_t)bh2 * 8 + dt) * 64 + kcb + kl) * 32 + lane] = o;
            }
        }
        return;
    }

#pragma unroll
    for (int mt = 0; mt < 2; mt++) {
        const int rg = blockIdx.y * 128 + wm * 32 + mt * 16;
        if (mode == 0) {
            const int r0 = rg + (lane >> 2);
#pragma unroll
            for (int nt = 0; nt < 8; nt++) {
                int col = cb + nt * 8;
                float bx = bias[col], by = bias[col + 1];
                *(float2*)(Out + (size_t)r0 * Cn + col) =
                    make_float2(d[mt][nt][0] + bx, d[mt][nt][1] + by);
                *(float2*)(Out + (size_t)(r0 + 8) * Cn + col) =
                    make_float2(d[mt][nt][2] + bx, d[mt][nt][3] + by);
            }
        } else if (mode == 1) {
            // Q A-fragments: scale 1/8, bias folded
            const int bq_ = rg >> 10;
            const int mtq = (rg & 1023) >> 4;
            const size_t base =
                ((size_t)((bq_ * Hn + h) * 64 + mtq) * 4) * 32 + lane;
#pragma unroll
            for (int dc = 0; dc < 4; dc++) {
                int c0 = cb + (2 * dc) * 8, c1 = cb + (2 * dc + 1) * 8;
                float b00 = bias[c0], b01 = bias[c0 + 1];
                float b10 = bias[c1], b11 = bias[c1 + 1];
                uint4 hh, ll;
                split2h((d[mt][2*dc][0]   + b00) * 0.125f,
                        (d[mt][2*dc][1]   + b01) * 0.125f, hh.x, ll.x);
                split2h((d[mt][2*dc][2]   + b00) * 0.125f,
                        (d[mt][2*dc][3]   + b01) * 0.125f, hh.y, ll.y);
                split2h((d[mt][2*dc+1][0] + b10) * 0.125f,
                        (d[mt][2*dc+1][1] + b11) * 0.125f, hh.z, ll.z);
                split2h((d[mt][2*dc+1][2] + b10) * 0.125f,
                        (d[mt][2*dc+1][3] + b11) * 0.125f, hh.w, ll.w);
                g_qfh[base + dc * 32] = hh;
                g_qfl[base + dc * 32] = ll;
            }
        } else {
            // K B-fragments (single fp16): two n8 key-tiles per m16
            const int bq_ = rg >> 10;
            const int ntk = (rg & 1023) >> 3;
            const size_t base =
                ((size_t)((bq_ * Hn + h) * 128 + ntk) * 4) * 32 + lane;
#pragma unroll
            for (int dc = 0; dc < 4; dc++) {
                int c0 = cb + (2 * dc) * 8, c1 = cb + (2 * dc + 1) * 8;
                float b00 = bias[c0], b01 = bias[c0 + 1];
                float b10 = bias[c1], b11 = bias[c1 + 1];
                uint2 t0, t1;
                t0.x = packh(d[mt][2*dc][0]   + b00, d[mt][2*dc][1]   + b01);
                t0.y = packh(d[mt][2*dc+1][0] + b10, d[mt][2*dc+1][1] + b11);
                t1.x = packh(d[mt][2*dc][2]   + b00, d[mt][2*dc][3]   + b01);
                t1.y = packh(d[mt][2*dc+1][2] + b10, d[mt][2*dc+1][3] + b11);
                g_kf[base + dc * 32]          = t0;
                g_kf[base + 4 * 32 + dc * 32] = t1;
            }
        }
    }
}

__global__ __launch_bounds__(256, 1)
void qkv_mma(const float* __restrict__ bq, const float* __restrict__ bk,
             const float* __restrict__ bv)
{
    const uint2* Wf = g_wf + (size_t)blockIdx.z * NTW * KT * 32;
    if (blockIdx.z == 0)      gemm_mma_body(g_xfh, g_xfl, Wf, bq, nullptr, 1);
    else if (blockIdx.z == 1) gemm_mma_body(g_xfh, g_xfl, Wf, bk, nullptr, 2);
    else                      gemm_mma_body(g_xfh, g_xfl, Wf, bv, nullptr, 3);
}

__global__ __launch_bounds__(256, 1)
void proj_mma(const float* __restrict__ bp, float* __restrict__ out)
{
    gemm_mma_body(g_yfh, g_yfl, g_wf + (size_t)3 * NTW * KT * 32, bp, out, 0);
}

// ---------------------------------------------------------------------------
// fp16 tensor-core flash attention.
// Block = (64 q-rows, head, batch), 128 threads = 4 warps (m16 each).
// CTA order reversed so the longest q-tiles launch first.
// 3-stage cp.async pipeline of 16KB K+V single-fp16 fragment tiles.
// ---------------------------------------------------------------------------
static constexpr int ATT_STG  = 16384;
static constexpr int ATT_SMEM = 3 * ATT_STG;   // 48KB

__global__ __launch_bounds__(128, 1)
void attn_mma()
{
    extern __shared__ __align__(16) char smem[];
    const uint32_t sbase = smem_u32(smem);
    const int tid  = threadIdx.x;
    const int lane = tid & 31;
    const int w    = tid >> 5;
    const int qt   = gridDim.x - 1 - blockIdx.x;   // longest tiles first
    const int h    = blockIdx.y;
    const int b    = blockIdx.z;
    const int bh   = b * Hn + h;
    const int nkt  = qt + 1;

    // Q fragments (hi/lo fp16, pre-scaled 1/8)
    uint4 qh[4], ql[4];
    {
        const uint4* Qh = g_qfh + ((size_t)(bh * 64 + qt * 4 + w) * 4) * 32 + lane;
        const uint4* Ql = g_qfl + ((size_t)(bh * 64 + qt * 4 + w) * 4) * 32 + lane;
#pragma unroll
        for (int dc = 0; dc < 4; dc++) { qh[dc] = Qh[dc * 32]; ql[dc] = Ql[dc * 32]; }
    }

    float o[8][4];
#pragma unroll
    for (int i = 0; i < 8; i++)
#pragma unroll
        for (int j = 0; j < 4; j++) o[i][j] = 0.f;
    float m[2] = {-1e30f, -1e30f}, l[2] = {0.f, 0.f};

    const uint2* Ksrc = g_kf  + (size_t)bh * 128 * 4 * 32;
    const uint2* Vsrc = g_vtf + (size_t)bh * 8 * 64 * 32;
    const int vkc = w;

    auto issue = [&](int slot, int kt) {
        uint32_t so = sbase + (uint32_t)slot * ATT_STG;
        const uint2* ks = Ksrc + (size_t)kt * 1024;
#pragma unroll
        for (int i = 0; i < 8; i++)
            cp8(so + (uint32_t)(i * 128 + tid) * 8, ks + i * 128 + tid);
#pragma unroll
        for (int dt = 0; dt < 8; dt++)
            cp8(so + 8192 + (uint32_t)((dt * 4 + vkc) * 32 + lane) * 8,
                Vsrc + ((size_t)dt * 64 + kt * 4 + vkc) * 32 + lane);
    };

    issue(0, 0); CP_COMMIT();
    if (nkt > 1) issue(1, 1);
    CP_COMMIT();

    for (int kt = 0; kt < nkt; kt++) {
        CP_WAIT1();
        __syncthreads();
        if (kt + 2 < nkt) issue((kt + 2) % 3, kt + 2);
        CP_COMMIT();

        const char* stK = smem + (size_t)(kt % 3) * ATT_STG;
        const char* stV = stK + 8192;

        // S = Q @ K^T (Q split, K single)
        float s[8][4];
#pragma unroll
        for (int i = 0; i < 8; i++)
#pragma unroll
            for (int j = 0; j < 4; j++) s[i][j] = 0.f;
#pragma unroll
        for (int dc = 0; dc < 4; dc++) {
#pragma unroll
            for (int nt = 0; nt < 8; nt++) {
                uint2 kb = *(const uint2*)(stK + ((nt * 4 + dc) * 32 + lane) * 8);
                mma16816(s[nt], (const uint32_t*)&qh[dc], kb.x, kb.y);
                mma16816(s[nt], (const uint32_t*)&ql[dc], kb.x, kb.y);
            }
        }

        // Causal mask (diagonal tile only)
        if (kt == qt) {
            int r0 = w * 16 + (lane >> 2);
            int c0 = (lane & 3) << 1;
#pragma unroll
            for (int nt = 0; nt < 8; nt++) {
                int col = nt * 8 + c0;
                if (col > r0)         s[nt][0] = -1e30f;
                if (col + 1 > r0)     s[nt][1] = -1e30f;
                if (col > r0 + 8)     s[nt][2] = -1e30f;
                if (col + 1 > r0 + 8) s[nt][3] = -1e30f;
            }
        }

        // Online softmax per row-half
#pragma unroll
        for (int i = 0; i < 2; i++) {
            float tm = -1e30f;
#pragma unroll
            for (int nt = 0; nt < 8; nt++)
                tm = fmaxf(tm, fmaxf(s[nt][2 * i], s[nt][2 * i + 1]));
            tm = fmaxf(tm, __shfl_xor_sync(0xffffffffu, tm, 1));
            tm = fmaxf(tm, __shfl_xor_sync(0xffffffffu, tm, 2));
            float newm = fmaxf(m[i], tm);
            float fac  = __expf(m[i] - newm);
            m[i] = newm;
            float rs = 0.f;
#pragma unroll
            for (int nt = 0; nt < 8; nt++) {
                float p0 = __expf(s[nt][2 * i] - newm);
                float p1 = __expf(s[nt][2 * i + 1] - newm);
                s[nt][2 * i] = p0;
                s[nt][2 * i + 1] = p1;
                rs += p0 + p1;
            }
            rs += __shfl_xor_sync(0xffffffffu, rs, 1);
            rs += __shfl_xor_sync(0xffffffffu, rs, 2);
            l[i] = l[i] * fac + rs;
#pragma unroll
            for (int dt = 0; dt < 8; dt++) {
                o[dt][2 * i]     *= fac;
                o[dt][2 * i + 1] *= fac;
            }
        }

        // O += P @ V  (P single fp16)
#pragma unroll
        for (int t = 0; t < 4; t++) {
            uint32_t ph[4];
            ph[0] = packh(s[2*t][0],   s[2*t][1]);
            ph[1] = packh(s[2*t][2],   s[2*t][3]);
            ph[2] = packh(s[2*t+1][0], s[2*t+1][1]);
            ph[3] = packh(s[2*t+1][2], s[2*t+1][3]);
#pragma unroll
            for (int dt = 0; dt < 8; dt++) {
                uint2 v = *(const uint2*)(stV + ((dt * 4 + t) * 32 + lane) * 8);
                mma16816(o[dt], ph, v.x, v.y);
            }
        }
    }

    // Epilogue: normalize, write y A-fragments (hi/lo) for proj GEMM
    const float inv0 = 1.f / l[0];
    const float inv1 = 1.f / l[1];
    const int mtg = b * 64 + qt * 4 + w;
#pragma unroll
    for (int dtc = 0; dtc < 4; dtc++) {
        uint4 hh, ll;
        split2h(o[2*dtc][0]   * inv0, o[2*dtc][1]   * inv0, hh.x, ll.x);
        split2h(o[2*dtc][2]   * inv1, o[2*dtc][3]   * inv1, hh.y, ll.y);
        split2h(o[2*dtc+1][0] * inv0, o[2*dtc+1][1] * inv0, hh.z, ll.z);
        split2h(o[2*dtc+1][2] * inv1, o[2*dtc+1][3] * inv1, hh.w, ll.w);
        size_t idx = ((size_t)mtg * KT + h * 4 + dtc) * 32 + lane;
        g_yfh[idx] = hh;
        g_yfl[idx] = ll;
    }
}

// ---------------------------------------------------------------------------
extern "C" void kernel_launch(void* const* d_in, const int* in_sizes, int n_in,
                              void* d_out, int out_size)
{
    const float* x  = (const float*)d_in[0];
    const float* Wq = (const float*)d_in[1];
    const float* bq = (const float*)d_in[2];
    const float* Wk = (const float*)d_in[3];
    const float* bk = (const float*)d_in[4];
    const float* Wv = (const float*)d_in[5];
    const float* bv = (const float*)d_in[6];
    const float* Wp = (const float*)d_in[7];
    const float* bp = (const float*)d_in[8];
    float* out = (float*)d_out;

    cudaFuncSetAttribute(qkv_mma, cudaFuncAttributeMaxDynamicSharedMemorySize, GEMM_SMEM);
    cudaFuncSetAttribute(proj_mma, cudaFuncAttributeMaxDynamicSharedMemorySize, GEMM_SMEM);
    cudaFuncSetAttribute(attn_mma, cudaFuncAttributeMaxDynamicSharedMemorySize, ATT_SMEM);

    split_xw_kernel<<<ACT_BLKS + W_BLKS, 256>>>(x, Wq, Wk, Wv, Wp);
    qkv_mma<<<dim3(Cn / 128, Mn / 128, 3), 256, GEMM_SMEM>>>(bq, bk, bv);
    attn_mma<<<dim3(Tn / 64, Hn, Bn), 128, ATT_SMEM>>>();
    proj_mma<<<dim3(Cn / 128, Mn / 128, 1), 256, GEMM_SMEM>>>(bp, out);
}